// round 6
// baseline (speedup 1.0000x reference)
#include <cuda_runtime.h>
#include <cuda_bf16.h>
#include <math.h>

// ---------------------------------------------------------------------------
// Problem dimensions (fixed by the reference setup)
// ---------------------------------------------------------------------------
#define B_SZ   8
#define N_PTS  500
#define M_HYP  144
#define M16    16
#define PS     8           // point slices per (b,m) for the residual kernel

#define C0 128
#define H0 48
#define W0 64
#define C1 64
#define H1 96
#define W1 128
#define C2 32
#define H2 192
#define W2 256

// transpose tile counts (32x32 tiles)
#define T0_TILES ((H0*W0/32) * (C0/32) * B_SZ)   // 96*4*8  = 3072
#define T1_TILES ((H1*W1/32) * (C1/32) * B_SZ)   // 384*2*8 = 6144
#define T2_TILES ((H2*W2/32) * (C2/32) * B_SZ)   // 1536*1*8= 12288

// ---------------------------------------------------------------------------
// Scratch (__device__ globals — no allocation allowed). D stored as bf16.
// ---------------------------------------------------------------------------
__device__ __nv_bfloat16 g_D0[(size_t)B_SZ * H0 * W0 * C0];   // q0-r0, channel-last
__device__ __nv_bfloat16 g_D1[(size_t)B_SZ * H1 * W1 * C1];
__device__ __nv_bfloat16 g_D2[(size_t)B_SZ * H2 * W2 * C2];
__device__ float g_Tcur[B_SZ * M_HYP * 16];
__device__ float g_resacc[PS * B_SZ * M16];
__device__ float g_costs[B_SZ * M_HYP];
__device__ unsigned g_ctr = 0;       // arrival counter (monotonic; modulo per launch)

// ---------------------------------------------------------------------------
// Threefry-2x32 (exactly JAX's 20-round schedule; KAT-verified)
// ---------------------------------------------------------------------------
__host__ __device__ __forceinline__ void threefry2x32(
    unsigned k0, unsigned k1, unsigned x0, unsigned x1,
    unsigned* o0, unsigned* o1)
{
  unsigned ks2 = k0 ^ k1 ^ 0x1BD11BDAu;
#define TFR(r) { x0 += x1; x1 = (x1 << (r)) | (x1 >> (32 - (r))); x1 ^= x0; }
  x0 += k0;  x1 += k1;
  TFR(13) TFR(15) TFR(26) TFR(6)
  x0 += k1;  x1 += ks2 + 1u;
  TFR(17) TFR(29) TFR(16) TFR(24)
  x0 += ks2; x1 += k0 + 2u;
  TFR(13) TFR(15) TFR(26) TFR(6)
  x0 += k0;  x1 += k1 + 3u;
  TFR(17) TFR(29) TFR(16) TFR(24)
  x0 += k1;  x1 += ks2 + 4u;
  TFR(13) TFR(15) TFR(26) TFR(6)
  x0 += ks2; x1 += k0 + 5u;
#undef TFR
  *o0 = x0; *o1 = x1;
}

// Giles/XLA erfinv (same coefficients as XLA ErfInv32)
__device__ __forceinline__ float erfinv_f(float x)
{
  float w = -log1pf(-x * x);
  float p;
  if (w < 5.0f) {
    w = w - 2.5f;
    p = 2.81022636e-08f;
    p = fmaf(p, w, 3.43273939e-07f);
    p = fmaf(p, w, -3.5233877e-06f);
    p = fmaf(p, w, -4.39150654e-06f);
    p = fmaf(p, w, 0.00021858087f);
    p = fmaf(p, w, -0.00125372503f);
    p = fmaf(p, w, -0.00417768164f);
    p = fmaf(p, w, 0.246640727f);
    p = fmaf(p, w, 1.50140941f);
  } else {
    w = sqrtf(w) - 3.0f;
    p = -0.000200214257f;
    p = fmaf(p, w, 0.000100950558f);
    p = fmaf(p, w, 0.00134934322f);
    p = fmaf(p, w, -0.00367342844f);
    p = fmaf(p, w, 0.00573950773f);
    p = fmaf(p, w, -0.0076224613f);
    p = fmaf(p, w, 0.00943887047f);
    p = fmaf(p, w, 1.00167406f);
    p = fmaf(p, w, 2.83297682f);
  }
  return p * x;
}

__device__ __forceinline__ float bits_to_normal(unsigned bits)
{
  float u = __uint_as_float((bits >> 9) | 0x3f800000u) - 1.0f;
  const float lo = -0.99999994f;
  float v = fmaxf(lo, u * 2.0f + lo);
  return 1.41421356237f * erfinv_f(v);
}

// PARTITIONABLE threefry: (y0,y1) = threefry(key; 0, j); 32-bit draw = y0 ^ y1.
__device__ __forceinline__ float jax_normal_elem(unsigned k0, unsigned k1, unsigned j)
{
  unsigned y0, y1;
  threefry2x32(k0, k1, 0u, j, &y0, &y1);
  return bits_to_normal(y0 ^ y1);
}

// ---------------------------------------------------------------------------
// se3_exp (matches reference element-by-element)
// ---------------------------------------------------------------------------
__device__ __forceinline__ void mat3mul(const float* A, const float* Bm, float* Cm)
{
#pragma unroll
  for (int i = 0; i < 3; i++)
#pragma unroll
    for (int j = 0; j < 3; j++)
      Cm[i * 3 + j] = A[i * 3 + 0] * Bm[0 * 3 + j] + A[i * 3 + 1] * Bm[1 * 3 + j] + A[i * 3 + 2] * Bm[2 * 3 + j];
}

__device__ void se3_exp6(const float xi[6], float T[16])
{
  float tx = xi[0], ty = xi[1], tz = xi[2];
  float wx = xi[3], wy = xi[4], wz = xi[5];
  float theta = fmaxf(sqrtf(wx * wx + wy * wy + wz * wz), 1e-8f);
  float kx = wx / theta, ky = wy / theta, kz = wz / theta;
  float K[9] = { 0.f, -kz, ky,  kz, 0.f, -kx,  -ky, kx, 0.f };
  float KK[9];
  mat3mul(K, K, KK);
  float st = sinf(theta);
  float ct = 1.0f - cosf(theta);
  float a  = ct / theta;
  float bb = 1.0f - st / theta;
  float R[9], V[9];
#pragma unroll
  for (int i = 0; i < 9; i++) {
    float e = (i == 0 || i == 4 || i == 8) ? 1.0f : 0.0f;
    R[i] = e + st * K[i] + ct * KK[i];
    V[i] = e + a  * K[i] + bb * KK[i];
  }
  float tox = V[0] * tx + V[1] * ty + V[2] * tz;
  float toy = V[3] * tx + V[4] * ty + V[5] * tz;
  float toz = V[6] * tx + V[7] * ty + V[8] * tz;
  T[0] = R[0]; T[1] = R[1]; T[2]  = R[2]; T[3]  = tox;
  T[4] = R[3]; T[5] = R[4]; T[6]  = R[5]; T[7]  = toy;
  T[8] = R[6]; T[9] = R[7]; T[10] = R[8]; T[11] = toz;
  T[12] = 0.f; T[13] = 0.f; T[14] = 0.f; T[15] = 1.f;
}

// ---------------------------------------------------------------------------
// Transpose helper: one 32x32 tile of D = q - r, (B,C,HW) -> (B,HW,C), bf16
// ---------------------------------------------------------------------------
__device__ __forceinline__ void do_tile(
    const float* __restrict__ q, const float* __restrict__ r,
    __nv_bfloat16* __restrict__ Dt, int C, int HW,
    int b, int c0, int hw0, float* tile /* [32][33] */)
{
  const float* qb = q + (size_t)b * C * HW;
  const float* rb = r + (size_t)b * C * HW;
  __nv_bfloat16* Db = Dt + (size_t)b * HW * C;
  int tx = threadIdx.x & 31, ty = threadIdx.x >> 5;
#pragma unroll
  for (int i = ty; i < 32; i += 8) {
    int c = c0 + i, hw = hw0 + tx;
    tile[i * 33 + tx] = qb[(size_t)c * HW + hw] - rb[(size_t)c * HW + hw];
  }
  __syncthreads();
  int tid = threadIdx.x;
#pragma unroll
  for (int idx = tid; idx < 32 * 16; idx += 256) {
    int row = idx >> 4;         // local hw
    int pr  = idx & 15;         // channel pair
    __nv_bfloat162 h = __floats2bfloat162_rn(tile[(2 * pr) * 33 + row],
                                             tile[(2 * pr + 1) * 33 + row]);
    *(__nv_bfloat162*)(Db + (size_t)(hw0 + row) * C + c0 + 2 * pr) = h;
  }
}

// ---------------------------------------------------------------------------
// prep kernel: blocks [0,8) = hypotheses; rest = transpose tiles of L0/L1/L2
// ---------------------------------------------------------------------------
__global__ __launch_bounds__(256) void prep_kernel(
    const float* __restrict__ q0, const float* __restrict__ r0,
    const float* __restrict__ q1, const float* __restrict__ r1,
    const float* __restrict__ q2, const float* __restrict__ r2,
    __nv_bfloat16* __restrict__ D0, __nv_bfloat16* __restrict__ D1,
    __nv_bfloat16* __restrict__ D2,
    const float* __restrict__ Tpred, unsigned k0, unsigned k1)
{
  __shared__ float tile[32 * 33];
  int blk = blockIdx.x;
  if (blk < B_SZ) {
    // hypotheses: one block per batch, threads 0..143 = hypothesis m
    int m = threadIdx.x;
    int b = blk;
    if (m >= M_HYP) return;
    float xi[6];
#pragma unroll
    for (int k = 0; k < 3; k++)
      xi[k] = jax_normal_elem(k0, k1, (unsigned)(m * 3 + k));
    int pi = m / 12, yj = m % 12;
    const float D2R = (float)(3.14159265358979323846 / 180.0);
    xi[3] = 0.0f;
    xi[4] = (-11.0f + 2.0f * (float)pi) * D2R;
    xi[5] = (-11.0f + 2.0f * (float)yj) * D2R;
    float dT[16];
    se3_exp6(xi, dT);
    const float* P = Tpred + b * 16;
    float* O = g_Tcur + (size_t)(b * M_HYP + m) * 16;
#pragma unroll
    for (int i = 0; i < 4; i++)
#pragma unroll
      for (int j = 0; j < 4; j++)
        O[i * 4 + j] = dT[i * 4 + 0] * P[0 * 4 + j] + dT[i * 4 + 1] * P[1 * 4 + j]
                     + dT[i * 4 + 2] * P[2 * 4 + j] + dT[i * 4 + 3] * P[3 * 4 + j];
    return;
  }
  blk -= B_SZ;
  if (blk < T0_TILES) {
    const int HWT = H0 * W0 / 32, CT = C0 / 32;      // 96, 4
    int b = blk / (HWT * CT);
    int rem = blk % (HWT * CT);
    int c0 = (rem / HWT) * 32, hw0 = (rem % HWT) * 32;
    do_tile(q0, r0, D0, C0, H0 * W0, b, c0, hw0, tile);
    return;
  }
  blk -= T0_TILES;
  if (blk < T1_TILES) {
    const int HWT = H1 * W1 / 32, CT = C1 / 32;      // 384, 2
    int b = blk / (HWT * CT);
    int rem = blk % (HWT * CT);
    int c0 = (rem / HWT) * 32, hw0 = (rem % HWT) * 32;
    do_tile(q1, r1, D1, C1, H1 * W1, b, c0, hw0, tile);
    return;
  }
  blk -= T1_TILES;
  {
    const int HWT = H2 * W2 / 32;                     // 1536, CT = 1
    int b = blk / HWT;
    int hw0 = (blk % HWT) * 32;
    do_tile(q2, r2, D2, C2, H2 * W2, b, 0, hw0, tile);
  }
}

// ---------------------------------------------------------------------------
// Residual + fused LM update.  grid = B*16*PS blocks, 256 threads (8 warps).
// Last-arriving block performs the update for all (b,m).
// ---------------------------------------------------------------------------
template <int CPL>
__global__ __launch_bounds__(256) void resup_kernel(
    const __nv_bfloat16* __restrict__ Dt, const float* __restrict__ Umap,
    const float* __restrict__ geo, const float* __restrict__ Kin,
    int C, int H, int W, float scale,
    unsigned uk0, unsigned uk1, float damping)
{
  int bm    = blockIdx.x >> 3;     // / PS
  int slice = blockIdx.x & 7;
  int b = bm >> 4, m = bm & 15;
  int lane = threadIdx.x & 31, wid = threadIdx.x >> 5;

  {
    const float* T = g_Tcur + (size_t)(b * M_HYP + m) * 16;
    float T00 = T[0], T01 = T[1], T02 = T[2],  T03 = T[3];
    float T10 = T[4], T11 = T[5], T12 = T[6],  T13 = T[7];
    float T20 = T[8], T21 = T[9], T22 = T[10], T23 = T[11];
    float fx = __ldg(Kin + b * 9 + 0) * scale, cx = __ldg(Kin + b * 9 + 2) * scale;
    float fy = __ldg(Kin + b * 9 + 4) * scale, cy = __ldg(Kin + b * 9 + 5) * scale;
    const __nv_bfloat16* Db = Dt + (size_t)b * H * W * C;
    const float* Ub = Umap + (size_t)b * H * W;
    const float* G  = geo + (size_t)b * N_PTS * 3;

    float Wm1 = (float)(W - 1), Hm1 = (float)(H - 1);
    float wacc = 0.0f;
    int nbeg = slice * 63 + wid;
    int nend = min(N_PTS, slice * 63 + 63);
    for (int n = nbeg; n < nend; n += 8) {
      float X = __ldg(G + n * 3 + 0);
      float Y = __ldg(G + n * 3 + 1);
      float Z = __ldg(G + n * 3 + 2);
      float px = T00 * X + T01 * Y + T02 * Z + T03;
      float py = T10 * X + T11 * Y + T12 * Z + T13;
      float pz = T20 * X + T21 * Y + T22 * Z + T23;
      float z  = fmaxf(pz, 1e-6f);
      float u  = fx * (px / z) + cx;
      float v  = fy * (py / z) + cy;
      float gx = 2.0f * u / Wm1 - 1.0f;
      float gy = 2.0f * v / Hm1 - 1.0f;
      float xs = fminf(fmaxf(((gx + 1.0f) * (float)W - 1.0f) * 0.5f, 0.0f), Wm1);
      float ys = fminf(fmaxf(((gy + 1.0f) * (float)H - 1.0f) * 0.5f, 0.0f), Hm1);
      float x0f = floorf(xs), y0f = floorf(ys);
      float x1f = fminf(x0f + 1.0f, Wm1), y1f = fminf(y0f + 1.0f, Hm1);
      float wx = xs - x0f, wy = ys - y0f;
      int x0 = (int)x0f, x1 = (int)x1f, y0 = (int)y0f, y1 = (int)y1f;
      float w00 = (1.0f - wx) * (1.0f - wy), w01 = wx * (1.0f - wy);
      float w10 = (1.0f - wx) * wy,          w11 = wx * wy;
      int r0 = y0 * W, r1 = y1 * W;

      float us = w00 * __ldg(Ub + r0 + x0) + w01 * __ldg(Ub + r0 + x1)
               + w10 * __ldg(Ub + r1 + x0) + w11 * __ldg(Ub + r1 + x1);

      float ssum = 0.0f;
      if constexpr (CPL == 4) {
        uint2 va = __ldg((const uint2*)(Db + (size_t)(r0 + x0) * C) + lane);
        uint2 vb = __ldg((const uint2*)(Db + (size_t)(r0 + x1) * C) + lane);
        uint2 vc = __ldg((const uint2*)(Db + (size_t)(r1 + x0) * C) + lane);
        uint2 vd = __ldg((const uint2*)(Db + (size_t)(r1 + x1) * C) + lane);
        float2 a0 = __bfloat1622float2(*(__nv_bfloat162*)&va.x);
        float2 a1 = __bfloat1622float2(*(__nv_bfloat162*)&va.y);
        float2 b0 = __bfloat1622float2(*(__nv_bfloat162*)&vb.x);
        float2 b1 = __bfloat1622float2(*(__nv_bfloat162*)&vb.y);
        float2 c0v = __bfloat1622float2(*(__nv_bfloat162*)&vc.x);
        float2 c1 = __bfloat1622float2(*(__nv_bfloat162*)&vc.y);
        float2 d0v = __bfloat1622float2(*(__nv_bfloat162*)&vd.x);
        float2 d1 = __bfloat1622float2(*(__nv_bfloat162*)&vd.y);
        float e0 = w00 * a0.x + w01 * b0.x + w10 * c0v.x + w11 * d0v.x;
        float e1 = w00 * a0.y + w01 * b0.y + w10 * c0v.y + w11 * d0v.y;
        float e2 = w00 * a1.x + w01 * b1.x + w10 * c1.x + w11 * d1.x;
        float e3 = w00 * a1.y + w01 * b1.y + w10 * c1.y + w11 * d1.y;
        ssum = e0 * e0 + e1 * e1 + e2 * e2 + e3 * e3;
      } else if constexpr (CPL == 2) {
        unsigned va = __ldg((const unsigned*)(Db + (size_t)(r0 + x0) * C) + lane);
        unsigned vb = __ldg((const unsigned*)(Db + (size_t)(r0 + x1) * C) + lane);
        unsigned vc = __ldg((const unsigned*)(Db + (size_t)(r1 + x0) * C) + lane);
        unsigned vd = __ldg((const unsigned*)(Db + (size_t)(r1 + x1) * C) + lane);
        float2 a = __bfloat1622float2(*(__nv_bfloat162*)&va);
        float2 bq = __bfloat1622float2(*(__nv_bfloat162*)&vb);
        float2 c = __bfloat1622float2(*(__nv_bfloat162*)&vc);
        float2 d = __bfloat1622float2(*(__nv_bfloat162*)&vd);
        float e0 = w00 * a.x + w01 * bq.x + w10 * c.x + w11 * d.x;
        float e1 = w00 * a.y + w01 * bq.y + w10 * c.y + w11 * d.y;
        ssum = e0 * e0 + e1 * e1;
      } else {
        float a  = __bfloat162float(__ldg(Db + (size_t)(r0 + x0) * C + lane));
        float bq = __bfloat162float(__ldg(Db + (size_t)(r0 + x1) * C + lane));
        float c  = __bfloat162float(__ldg(Db + (size_t)(r1 + x0) * C + lane));
        float d  = __bfloat162float(__ldg(Db + (size_t)(r1 + x1) * C + lane));
        float e0 = w00 * a + w01 * bq + w10 * c + w11 * d;
        ssum = e0 * e0;
      }
      wacc += us * ssum;
    }
#pragma unroll
    for (int o = 16; o; o >>= 1) wacc += __shfl_xor_sync(0xffffffffu, wacc, o);
    __shared__ float wp[8];
    if (lane == 0) wp[wid] = wacc;
    __syncthreads();
    if (threadIdx.x == 0) {
      float s = 0.0f;
#pragma unroll
      for (int w = 0; w < 8; w++) s += wp[w];
      g_resacc[slice * (B_SZ * M16) + bm] = s;
      __threadfence();
    }
  }

  // ---- last-block LM update ----
  __shared__ int isLast;
  if (threadIdx.x == 0) {
    unsigned old = atomicAdd(&g_ctr, 1u);
    isLast = ((old % gridDim.x) == gridDim.x - 1u) ? 1 : 0;
  }
  __syncthreads();
  if (!isLast) return;
  __threadfence();    // acquire: all blocks' resacc visible

  for (int i = threadIdx.x; i < B_SZ * M_HYP; i += 256) {
    int ub = i / M_HYP, um = i % M_HYP;
    float res = 0.0f;
    if (um < M16) {
      float s = 0.0f;
#pragma unroll
      for (int p = 0; p < PS; p++) s += g_resacc[p * (B_SZ * M16) + ub * M16 + um];
      res = s / (float)N_PTS;
    }
    g_costs[i] = res;

    float xi[6];
    unsigned base = (unsigned)(i * 6);
    float s1 = -damping * res;
#pragma unroll
    for (int k = 0; k < 6; k++) {
      float nz = jax_normal_elem(uk0, uk1, base + (unsigned)k);
      xi[k] = s1 * nz * 0.01f;
    }
    float D[16];
    se3_exp6(xi, D);
    float* T = g_Tcur + (size_t)i * 16;
    float Told[16];
#pragma unroll
    for (int t = 0; t < 16; t++) Told[t] = T[t];
#pragma unroll
    for (int r = 0; r < 4; r++)
#pragma unroll
      for (int cc = 0; cc < 4; cc++)
        T[r * 4 + cc] = D[r * 4 + 0] * Told[0 * 4 + cc] + D[r * 4 + 1] * Told[1 * 4 + cc]
                      + D[r * 4 + 2] * Told[2 * 4 + cc] + D[r * 4 + 3] * Told[3 * 4 + cc];
  }
}

// ---------------------------------------------------------------------------
// Kernel: geodesic + argmin + output.  grid = B blocks x 144 threads.
// ---------------------------------------------------------------------------
__global__ void final_kernel(const float* __restrict__ Tpred, float* __restrict__ out)
{
  int b = blockIdx.x;
  int m = threadIdx.x;
  __shared__ float tot[M_HYP];
  if (m < M_HYP) {
    const float* P = Tpred + b * 16;
    float Ri[9] = { P[0], P[4], P[8],  P[1], P[5], P[9],  P[2], P[6], P[10] };
    float tix = -(Ri[0] * P[3] + Ri[1] * P[7] + Ri[2] * P[11]);
    float tiy = -(Ri[3] * P[3] + Ri[4] * P[7] + Ri[5] * P[11]);
    float tiz = -(Ri[6] * P[3] + Ri[7] * P[7] + Ri[8] * P[11]);
    float Ti[16] = { Ri[0], Ri[1], Ri[2], tix,
                     Ri[3], Ri[4], Ri[5], tiy,
                     Ri[6], Ri[7], Ri[8], tiz,
                     0.f, 0.f, 0.f, 1.f };
    const float* Tc = g_Tcur + (size_t)(b * M_HYP + m) * 16;
    float A[16];
#pragma unroll
    for (int i = 0; i < 4; i++)
#pragma unroll
      for (int j = 0; j < 4; j++)
        A[i * 4 + j] = Tc[i * 4 + 0] * Ti[0 * 4 + j] + Tc[i * 4 + 1] * Ti[1 * 4 + j]
                     + Tc[i * 4 + 2] * Ti[2 * 4 + j] + Tc[i * 4 + 3] * Ti[3 * 4 + j];
    float cos_a = (A[0] + A[5] + A[10] - 1.0f) * 0.5f;
    const float CL = (float)(1.0 - 1e-7);
    cos_a = fminf(fmaxf(cos_a, -CL), CL);
    float theta = acosf(cos_a);
    float th = fmaxf(theta, 1e-8f);
    float sn = fmaxf(sinf(th), 1e-8f);
    float wx = (A[9] - A[6]) / (2.0f * sn) * th;
    float wy = (A[2] - A[8]) / (2.0f * sn) * th;
    float wz = (A[4] - A[1]) / (2.0f * sn) * th;
    if (fabsf(theta) < 1e-6f) { wx = 0.f; wy = 0.f; wz = 0.f; }
    float tx = A[3], ty = A[7], tz = A[11];
    float geod = sqrtf(tx * tx + ty * ty + tz * tz + wx * wx + wy * wy + wz * wz);
    float c = g_costs[b * M_HYP + m];
    tot[m] = c + geod;
    out[128 + b * M_HYP + m] = c;
  }
  __syncthreads();
  if (m == 0) {
    int best = 0;
    float bv = tot[0];
    for (int i = 1; i < M_HYP; i++)
      if (tot[i] < bv) { bv = tot[i]; best = i; }
    const float* Tb = g_Tcur + (size_t)(b * M_HYP + best) * 16;
#pragma unroll
    for (int i = 0; i < 16; i++) out[b * 16 + i] = Tb[i];
  }
}

// ---------------------------------------------------------------------------
// Host launch
// ---------------------------------------------------------------------------
extern "C" void kernel_launch(void* const* d_in, const int* in_sizes, int n_in,
                              void* d_out, int out_size)
{
  const float* T_pred = (const float*)d_in[0];
  const float* geo    = (const float*)d_in[1];
  const float* Kin    = (const float*)d_in[2];
  const float* q0 = (const float*)d_in[3];
  const float* q1 = (const float*)d_in[4];
  const float* q2 = (const float*)d_in[5];
  const float* r0 = (const float*)d_in[6];
  const float* r1 = (const float*)d_in[7];
  const float* r2 = (const float*)d_in[8];
  const float* u0 = (const float*)d_in[9];
  const float* u1 = (const float*)d_in[10];
  const float* u2 = (const float*)d_in[11];
  float* out = (float*)d_out;

  __nv_bfloat16 *D0p, *D1p, *D2p;
  cudaGetSymbolAddress((void**)&D0p, g_D0);
  cudaGetSymbolAddress((void**)&D1p, g_D1);
  cudaGetSymbolAddress((void**)&D2p, g_D2);

  unsigned hk0, hk1;
  threefry2x32(0u, 42u, 0u, 0u, &hk0, &hk1);

  // one prep launch: hypotheses + all three transposed bf16 diffs
  int prep_blocks = B_SZ + T0_TILES + T1_TILES + T2_TILES;
  prep_kernel<<<prep_blocks, 256>>>(q0, r0, q1, r1, q2, r2, D0p, D1p, D2p,
                                    T_pred, hk0, hk1);

  const int iters[3] = { 2, 3, 4 };
  const int grid_res = B_SZ * M16 * PS;    // 1024 blocks
  for (int level = 0; level < 3; level++) {
    float scale = 1.0f / (4.0f / (float)(1 << level));
    float damping = (float)(0.001 * pow(0.5, (double)level));
    for (int it = 0; it < iters[level]; it++) {
      unsigned ik0, ik1;
      threefry2x32(0u, 42u, 0u, (unsigned)(100 + level * 10 + it), &ik0, &ik1);
      if (level == 0)
        resup_kernel<4><<<grid_res, 256>>>(D0p, u0, geo, Kin, C0, H0, W0, scale, ik0, ik1, damping);
      else if (level == 1)
        resup_kernel<2><<<grid_res, 256>>>(D1p, u1, geo, Kin, C1, H1, W1, scale, ik0, ik1, damping);
      else
        resup_kernel<1><<<grid_res, 256>>>(D2p, u2, geo, Kin, C2, H2, W2, scale, ik0, ik1, damping);
    }
  }

  final_kernel<<<B_SZ, M_HYP>>>(T_pred, out);
  (void)in_sizes; (void)n_in; (void)out_size;
}

// round 7
// speedup vs baseline: 1.8622x; 1.8622x over previous
#include <cuda_runtime.h>
#include <cuda_bf16.h>
#include <math.h>

// ---------------------------------------------------------------------------
// Problem dimensions (fixed by the reference setup)
// ---------------------------------------------------------------------------
#define B_SZ   8
#define N_PTS  500
#define M_HYP  144
#define M16    16
#define PS     8           // point slices per (b,m) for the residual kernel
#define N_ITER 9

#define C0 128
#define H0 48
#define W0 64
#define C1 64
#define H1 96
#define W1 128
#define C2 32
#define H2 192
#define W2 256

// transpose tile counts (32x32 tiles)
#define T0_TILES ((H0*W0/32) * (C0/32) * B_SZ)   // 3072
#define T1_TILES ((H1*W1/32) * (C1/32) * B_SZ)   // 6144
#define T2_TILES ((H2*W2/32) * (C2/32) * B_SZ)   // 12288

// ---------------------------------------------------------------------------
// Scratch (__device__ globals — no allocation allowed). D stored as bf16.
// ---------------------------------------------------------------------------
__device__ __nv_bfloat16 g_D0[(size_t)B_SZ * H0 * W0 * C0];   // q0-r0, channel-last
__device__ __nv_bfloat16 g_D1[(size_t)B_SZ * H1 * W1 * C1];
__device__ __nv_bfloat16 g_D2[(size_t)B_SZ * H2 * W2 * C2];
__device__ float g_Tcur[B_SZ * M_HYP * 16];
__device__ float g_resacc[PS * B_SZ * M16];
__device__ float g_costs[B_SZ * M_HYP];
__device__ float g_noise[N_ITER * B_SZ * M16 * 6];   // precomputed LM noise (m<16 only)

// ---------------------------------------------------------------------------
// Threefry-2x32 (exactly JAX's 20-round schedule; KAT-verified)
// ---------------------------------------------------------------------------
__host__ __device__ __forceinline__ void threefry2x32(
    unsigned k0, unsigned k1, unsigned x0, unsigned x1,
    unsigned* o0, unsigned* o1)
{
  unsigned ks2 = k0 ^ k1 ^ 0x1BD11BDAu;
#define TFR(r) { x0 += x1; x1 = (x1 << (r)) | (x1 >> (32 - (r))); x1 ^= x0; }
  x0 += k0;  x1 += k1;
  TFR(13) TFR(15) TFR(26) TFR(6)
  x0 += k1;  x1 += ks2 + 1u;
  TFR(17) TFR(29) TFR(16) TFR(24)
  x0 += ks2; x1 += k0 + 2u;
  TFR(13) TFR(15) TFR(26) TFR(6)
  x0 += k0;  x1 += k1 + 3u;
  TFR(17) TFR(29) TFR(16) TFR(24)
  x0 += k1;  x1 += ks2 + 4u;
  TFR(13) TFR(15) TFR(26) TFR(6)
  x0 += ks2; x1 += k0 + 5u;
#undef TFR
  *o0 = x0; *o1 = x1;
}

// Giles/XLA erfinv (same coefficients as XLA ErfInv32)
__device__ __forceinline__ float erfinv_f(float x)
{
  float w = -log1pf(-x * x);
  float p;
  if (w < 5.0f) {
    w = w - 2.5f;
    p = 2.81022636e-08f;
    p = fmaf(p, w, 3.43273939e-07f);
    p = fmaf(p, w, -3.5233877e-06f);
    p = fmaf(p, w, -4.39150654e-06f);
    p = fmaf(p, w, 0.00021858087f);
    p = fmaf(p, w, -0.00125372503f);
    p = fmaf(p, w, -0.00417768164f);
    p = fmaf(p, w, 0.246640727f);
    p = fmaf(p, w, 1.50140941f);
  } else {
    w = sqrtf(w) - 3.0f;
    p = -0.000200214257f;
    p = fmaf(p, w, 0.000100950558f);
    p = fmaf(p, w, 0.00134934322f);
    p = fmaf(p, w, -0.00367342844f);
    p = fmaf(p, w, 0.00573950773f);
    p = fmaf(p, w, -0.0076224613f);
    p = fmaf(p, w, 0.00943887047f);
    p = fmaf(p, w, 1.00167406f);
    p = fmaf(p, w, 2.83297682f);
  }
  return p * x;
}

__device__ __forceinline__ float bits_to_normal(unsigned bits)
{
  float u = __uint_as_float((bits >> 9) | 0x3f800000u) - 1.0f;
  const float lo = -0.99999994f;
  float v = fmaxf(lo, u * 2.0f + lo);
  return 1.41421356237f * erfinv_f(v);
}

// PARTITIONABLE threefry: (y0,y1) = threefry(key; 0, j); 32-bit draw = y0 ^ y1.
__device__ __forceinline__ float jax_normal_elem(unsigned k0, unsigned k1, unsigned j)
{
  unsigned y0, y1;
  threefry2x32(k0, k1, 0u, j, &y0, &y1);
  return bits_to_normal(y0 ^ y1);
}

// ---------------------------------------------------------------------------
// se3_exp (matches reference element-by-element)
// ---------------------------------------------------------------------------
__device__ __forceinline__ void mat3mul(const float* A, const float* Bm, float* Cm)
{
#pragma unroll
  for (int i = 0; i < 3; i++)
#pragma unroll
    for (int j = 0; j < 3; j++)
      Cm[i * 3 + j] = A[i * 3 + 0] * Bm[0 * 3 + j] + A[i * 3 + 1] * Bm[1 * 3 + j] + A[i * 3 + 2] * Bm[2 * 3 + j];
}

__device__ void se3_exp6(const float xi[6], float T[16])
{
  float tx = xi[0], ty = xi[1], tz = xi[2];
  float wx = xi[3], wy = xi[4], wz = xi[5];
  float theta = fmaxf(sqrtf(wx * wx + wy * wy + wz * wz), 1e-8f);
  float kx = wx / theta, ky = wy / theta, kz = wz / theta;
  float K[9] = { 0.f, -kz, ky,  kz, 0.f, -kx,  -ky, kx, 0.f };
  float KK[9];
  mat3mul(K, K, KK);
  float st = sinf(theta);
  float ct = 1.0f - cosf(theta);
  float a  = ct / theta;
  float bb = 1.0f - st / theta;
  float R[9], V[9];
#pragma unroll
  for (int i = 0; i < 9; i++) {
    float e = (i == 0 || i == 4 || i == 8) ? 1.0f : 0.0f;
    R[i] = e + st * K[i] + ct * KK[i];
    V[i] = e + a  * K[i] + bb * KK[i];
  }
  float tox = V[0] * tx + V[1] * ty + V[2] * tz;
  float toy = V[3] * tx + V[4] * ty + V[5] * tz;
  float toz = V[6] * tx + V[7] * ty + V[8] * tz;
  T[0] = R[0]; T[1] = R[1]; T[2]  = R[2]; T[3]  = tox;
  T[4] = R[3]; T[5] = R[4]; T[6]  = R[5]; T[7]  = toy;
  T[8] = R[6]; T[9] = R[7]; T[10] = R[8]; T[11] = toz;
  T[12] = 0.f; T[13] = 0.f; T[14] = 0.f; T[15] = 1.f;
}

// ---------------------------------------------------------------------------
// Transpose helper: one 32x32 tile of D = q - r, (B,C,HW) -> (B,HW,C), bf16
// ---------------------------------------------------------------------------
__device__ __forceinline__ void do_tile(
    const float* __restrict__ q, const float* __restrict__ r,
    __nv_bfloat16* __restrict__ Dt, int C, int HW,
    int b, int c0, int hw0, float* tile /* [32][33] */)
{
  const float* qb = q + (size_t)b * C * HW;
  const float* rb = r + (size_t)b * C * HW;
  __nv_bfloat16* Db = Dt + (size_t)b * HW * C;
  int tx = threadIdx.x & 31, ty = threadIdx.x >> 5;
#pragma unroll
  for (int i = ty; i < 32; i += 8) {
    int c = c0 + i, hw = hw0 + tx;
    tile[i * 33 + tx] = qb[(size_t)c * HW + hw] - rb[(size_t)c * HW + hw];
  }
  __syncthreads();
  int tid = threadIdx.x;
#pragma unroll
  for (int idx = tid; idx < 32 * 16; idx += 256) {
    int row = idx >> 4;         // local hw
    int pr  = idx & 15;         // channel pair
    __nv_bfloat162 h = __floats2bfloat162_rn(tile[(2 * pr) * 33 + row],
                                             tile[(2 * pr + 1) * 33 + row]);
    *(__nv_bfloat162*)(Db + (size_t)(hw0 + row) * C + c0 + 2 * pr) = h;
  }
}

// ---------------------------------------------------------------------------
// prep kernel: blocks [0,8) = hypotheses; block 8 = noise precompute + cost
// zeroing; rest = transpose tiles of L0/L1/L2
// ---------------------------------------------------------------------------
__global__ __launch_bounds__(256) void prep_kernel(
    const float* __restrict__ q0, const float* __restrict__ r0,
    const float* __restrict__ q1, const float* __restrict__ r1,
    const float* __restrict__ q2, const float* __restrict__ r2,
    __nv_bfloat16* __restrict__ D0, __nv_bfloat16* __restrict__ D1,
    __nv_bfloat16* __restrict__ D2,
    const float* __restrict__ Tpred, unsigned k0, unsigned k1)
{
  __shared__ float tile[32 * 33];
  int blk = blockIdx.x;
  if (blk < B_SZ) {
    // hypotheses: one block per batch, threads 0..143 = hypothesis m
    int m = threadIdx.x;
    int b = blk;
    if (m >= M_HYP) return;
    float xi[6];
#pragma unroll
    for (int k = 0; k < 3; k++)
      xi[k] = jax_normal_elem(k0, k1, (unsigned)(m * 3 + k));
    int pi = m / 12, yj = m % 12;
    const float D2R = (float)(3.14159265358979323846 / 180.0);
    xi[3] = 0.0f;
    xi[4] = (-11.0f + 2.0f * (float)pi) * D2R;
    xi[5] = (-11.0f + 2.0f * (float)yj) * D2R;
    float dT[16];
    se3_exp6(xi, dT);
    const float* P = Tpred + b * 16;
    float* O = g_Tcur + (size_t)(b * M_HYP + m) * 16;
#pragma unroll
    for (int i = 0; i < 4; i++)
#pragma unroll
      for (int j = 0; j < 4; j++)
        O[i * 4 + j] = dT[i * 4 + 0] * P[0 * 4 + j] + dT[i * 4 + 1] * P[1 * 4 + j]
                     + dT[i * 4 + 2] * P[2 * 4 + j] + dT[i * 4 + 3] * P[3 * 4 + j];
    return;
  }
  blk -= B_SZ;
  if (blk == 0) {
    // noise precompute for all 9 iterations (m<16 only) + zero g_costs
    const int LI[N_ITER] = {100, 101, 110, 111, 112, 120, 121, 122, 123};
    int tid = threadIdx.x;
    for (int it = 0; it < N_ITER; it++) {
      unsigned ik0, ik1;
      threefry2x32(0u, 42u, 0u, (unsigned)LI[it], &ik0, &ik1);
      for (int idx = tid; idx < B_SZ * M16 * 6; idx += 256) {
        int i = idx / 6, k = idx % 6;
        int b = i >> 4, m = i & 15;
        unsigned j = (unsigned)((b * M_HYP + m) * 6 + k);
        g_noise[it * (B_SZ * M16 * 6) + idx] = jax_normal_elem(ik0, ik1, j);
      }
    }
    for (int idx = tid; idx < B_SZ * M_HYP; idx += 256)
      g_costs[idx] = 0.0f;
    return;
  }
  blk -= 1;
  if (blk < T0_TILES) {
    const int HWT = H0 * W0 / 32, CT = C0 / 32;
    int b = blk / (HWT * CT);
    int rem = blk % (HWT * CT);
    int c0 = (rem / HWT) * 32, hw0 = (rem % HWT) * 32;
    do_tile(q0, r0, D0, C0, H0 * W0, b, c0, hw0, tile);
    return;
  }
  blk -= T0_TILES;
  if (blk < T1_TILES) {
    const int HWT = H1 * W1 / 32, CT = C1 / 32;
    int b = blk / (HWT * CT);
    int rem = blk % (HWT * CT);
    int c0 = (rem / HWT) * 32, hw0 = (rem % HWT) * 32;
    do_tile(q1, r1, D1, C1, H1 * W1, b, c0, hw0, tile);
    return;
  }
  blk -= T1_TILES;
  {
    const int HWT = H2 * W2 / 32;
    int b = blk / HWT;
    int hw0 = (blk % HWT) * 32;
    do_tile(q2, r2, D2, C2, H2 * W2, b, 0, hw0, tile);
  }
}

// ---------------------------------------------------------------------------
// Residuals (round-5 proven version).  grid = B*16*PS blocks, 256 threads.
// ---------------------------------------------------------------------------
template <int CPL>
__global__ __launch_bounds__(256) void residual_kernel(
    const __nv_bfloat16* __restrict__ Dt, const float* __restrict__ Umap,
    const float* __restrict__ geo, const float* __restrict__ Kin,
    int C, int H, int W, float scale)
{
  int bm    = blockIdx.x >> 3;     // / PS
  int slice = blockIdx.x & 7;
  int b = bm >> 4, m = bm & 15;
  int lane = threadIdx.x & 31, wid = threadIdx.x >> 5;

  const float* T = g_Tcur + (size_t)(b * M_HYP + m) * 16;
  float T00 = T[0], T01 = T[1], T02 = T[2],  T03 = T[3];
  float T10 = T[4], T11 = T[5], T12 = T[6],  T13 = T[7];
  float T20 = T[8], T21 = T[9], T22 = T[10], T23 = T[11];
  float fx = __ldg(Kin + b * 9 + 0) * scale, cx = __ldg(Kin + b * 9 + 2) * scale;
  float fy = __ldg(Kin + b * 9 + 4) * scale, cy = __ldg(Kin + b * 9 + 5) * scale;
  const __nv_bfloat16* Db = Dt + (size_t)b * H * W * C;
  const float* Ub = Umap + (size_t)b * H * W;
  const float* G  = geo + (size_t)b * N_PTS * 3;

  float Wm1 = (float)(W - 1), Hm1 = (float)(H - 1);
  float wacc = 0.0f;
  int nbeg = slice * 63 + wid;
  int nend = min(N_PTS, slice * 63 + 63);
  for (int n = nbeg; n < nend; n += 8) {
    float X = __ldg(G + n * 3 + 0);
    float Y = __ldg(G + n * 3 + 1);
    float Z = __ldg(G + n * 3 + 2);
    float px = T00 * X + T01 * Y + T02 * Z + T03;
    float py = T10 * X + T11 * Y + T12 * Z + T13;
    float pz = T20 * X + T21 * Y + T22 * Z + T23;
    float z  = fmaxf(pz, 1e-6f);
    float u  = fx * (px / z) + cx;
    float v  = fy * (py / z) + cy;
    float gx = 2.0f * u / Wm1 - 1.0f;
    float gy = 2.0f * v / Hm1 - 1.0f;
    float xs = fminf(fmaxf(((gx + 1.0f) * (float)W - 1.0f) * 0.5f, 0.0f), Wm1);
    float ys = fminf(fmaxf(((gy + 1.0f) * (float)H - 1.0f) * 0.5f, 0.0f), Hm1);
    float x0f = floorf(xs), y0f = floorf(ys);
    float x1f = fminf(x0f + 1.0f, Wm1), y1f = fminf(y0f + 1.0f, Hm1);
    float wx = xs - x0f, wy = ys - y0f;
    int x0 = (int)x0f, x1 = (int)x1f, y0 = (int)y0f, y1 = (int)y1f;
    float w00 = (1.0f - wx) * (1.0f - wy), w01 = wx * (1.0f - wy);
    float w10 = (1.0f - wx) * wy,          w11 = wx * wy;
    int r0 = y0 * W, r1 = y1 * W;

    float us = w00 * __ldg(Ub + r0 + x0) + w01 * __ldg(Ub + r0 + x1)
             + w10 * __ldg(Ub + r1 + x0) + w11 * __ldg(Ub + r1 + x1);

    float ssum = 0.0f;
    if constexpr (CPL == 4) {
      uint2 va = __ldg((const uint2*)(Db + (size_t)(r0 + x0) * C) + lane);
      uint2 vb = __ldg((const uint2*)(Db + (size_t)(r0 + x1) * C) + lane);
      uint2 vc = __ldg((const uint2*)(Db + (size_t)(r1 + x0) * C) + lane);
      uint2 vd = __ldg((const uint2*)(Db + (size_t)(r1 + x1) * C) + lane);
      float2 a0 = __bfloat1622float2(*(__nv_bfloat162*)&va.x);
      float2 a1 = __bfloat1622float2(*(__nv_bfloat162*)&va.y);
      float2 b0 = __bfloat1622float2(*(__nv_bfloat162*)&vb.x);
      float2 b1 = __bfloat1622float2(*(__nv_bfloat162*)&vb.y);
      float2 c0v = __bfloat1622float2(*(__nv_bfloat162*)&vc.x);
      float2 c1 = __bfloat1622float2(*(__nv_bfloat162*)&vc.y);
      float2 d0v = __bfloat1622float2(*(__nv_bfloat162*)&vd.x);
      float2 d1 = __bfloat1622float2(*(__nv_bfloat162*)&vd.y);
      float e0 = w00 * a0.x + w01 * b0.x + w10 * c0v.x + w11 * d0v.x;
      float e1 = w00 * a0.y + w01 * b0.y + w10 * c0v.y + w11 * d0v.y;
      float e2 = w00 * a1.x + w01 * b1.x + w10 * c1.x + w11 * d1.x;
      float e3 = w00 * a1.y + w01 * b1.y + w10 * c1.y + w11 * d1.y;
      ssum = e0 * e0 + e1 * e1 + e2 * e2 + e3 * e3;
    } else if constexpr (CPL == 2) {
      unsigned va = __ldg((const unsigned*)(Db + (size_t)(r0 + x0) * C) + lane);
      unsigned vb = __ldg((const unsigned*)(Db + (size_t)(r0 + x1) * C) + lane);
      unsigned vc = __ldg((const unsigned*)(Db + (size_t)(r1 + x0) * C) + lane);
      unsigned vd = __ldg((const unsigned*)(Db + (size_t)(r1 + x1) * C) + lane);
      float2 a = __bfloat1622float2(*(__nv_bfloat162*)&va);
      float2 bq = __bfloat1622float2(*(__nv_bfloat162*)&vb);
      float2 c = __bfloat1622float2(*(__nv_bfloat162*)&vc);
      float2 d = __bfloat1622float2(*(__nv_bfloat162*)&vd);
      float e0 = w00 * a.x + w01 * bq.x + w10 * c.x + w11 * d.x;
      float e1 = w00 * a.y + w01 * bq.y + w10 * c.y + w11 * d.y;
      ssum = e0 * e0 + e1 * e1;
    } else {
      float a  = __bfloat162float(__ldg(Db + (size_t)(r0 + x0) * C + lane));
      float bq = __bfloat162float(__ldg(Db + (size_t)(r0 + x1) * C + lane));
      float c  = __bfloat162float(__ldg(Db + (size_t)(r1 + x0) * C + lane));
      float d  = __bfloat162float(__ldg(Db + (size_t)(r1 + x1) * C + lane));
      float e0 = w00 * a + w01 * bq + w10 * c + w11 * d;
      ssum = e0 * e0;
    }
    wacc += us * ssum;
  }
#pragma unroll
  for (int o = 16; o; o >>= 1) wacc += __shfl_xor_sync(0xffffffffu, wacc, o);
  __shared__ float wp[8];
  if (lane == 0) wp[wid] = wacc;
  __syncthreads();
  if (threadIdx.x == 0) {
    float s = 0.0f;
#pragma unroll
    for (int w = 0; w < 8; w++) s += wp[w];
    g_resacc[slice * (B_SZ * M16) + bm] = s;
  }
}

// ---------------------------------------------------------------------------
// LM update: only the 128 (b, m<16) items do real work.  1 block x 128 thr.
// Noise precomputed in prep.
// ---------------------------------------------------------------------------
__global__ void update_kernel(int iter, float damping)
{
  int i = threadIdx.x;              // 0..127
  if (i >= B_SZ * M16) return;
  int b = i >> 4, m = i & 15;
  float s = 0.0f;
#pragma unroll
  for (int p = 0; p < PS; p++) s += g_resacc[p * (B_SZ * M16) + i];
  float res = s / (float)N_PTS;
  g_costs[b * M_HYP + m] = res;

  const float* nz = g_noise + (iter * (B_SZ * M16) + i) * 6;
  float s1 = -damping * res * 0.01f;
  float xi[6];
#pragma unroll
  for (int k = 0; k < 6; k++) xi[k] = s1 * nz[k];
  float D[16];
  se3_exp6(xi, D);
  float* T = g_Tcur + (size_t)(b * M_HYP + m) * 16;
  float Told[16];
#pragma unroll
  for (int t = 0; t < 16; t++) Told[t] = T[t];
#pragma unroll
  for (int r = 0; r < 4; r++)
#pragma unroll
    for (int cc = 0; cc < 4; cc++)
      T[r * 4 + cc] = D[r * 4 + 0] * Told[0 * 4 + cc] + D[r * 4 + 1] * Told[1 * 4 + cc]
                    + D[r * 4 + 2] * Told[2 * 4 + cc] + D[r * 4 + 3] * Told[3 * 4 + cc];
}

// ---------------------------------------------------------------------------
// Kernel: geodesic + argmin + output.  grid = B blocks x 144 threads.
// ---------------------------------------------------------------------------
__global__ void final_kernel(const float* __restrict__ Tpred, float* __restrict__ out)
{
  int b = blockIdx.x;
  int m = threadIdx.x;
  __shared__ float tot[M_HYP];
  if (m < M_HYP) {
    const float* P = Tpred + b * 16;
    float Ri[9] = { P[0], P[4], P[8],  P[1], P[5], P[9],  P[2], P[6], P[10] };
    float tix = -(Ri[0] * P[3] + Ri[1] * P[7] + Ri[2] * P[11]);
    float tiy = -(Ri[3] * P[3] + Ri[4] * P[7] + Ri[5] * P[11]);
    float tiz = -(Ri[6] * P[3] + Ri[7] * P[7] + Ri[8] * P[11]);
    float Ti[16] = { Ri[0], Ri[1], Ri[2], tix,
                     Ri[3], Ri[4], Ri[5], tiy,
                     Ri[6], Ri[7], Ri[8], tiz,
                     0.f, 0.f, 0.f, 1.f };
    const float* Tc = g_Tcur + (size_t)(b * M_HYP + m) * 16;
    float A[16];
#pragma unroll
    for (int i = 0; i < 4; i++)
#pragma unroll
      for (int j = 0; j < 4; j++)
        A[i * 4 + j] = Tc[i * 4 + 0] * Ti[0 * 4 + j] + Tc[i * 4 + 1] * Ti[1 * 4 + j]
                     + Tc[i * 4 + 2] * Ti[2 * 4 + j] + Tc[i * 4 + 3] * Ti[3 * 4 + j];
    float cos_a = (A[0] + A[5] + A[10] - 1.0f) * 0.5f;
    const float CL = (float)(1.0 - 1e-7);
    cos_a = fminf(fmaxf(cos_a, -CL), CL);
    float theta = acosf(cos_a);
    float th = fmaxf(theta, 1e-8f);
    float sn = fmaxf(sinf(th), 1e-8f);
    float wx = (A[9] - A[6]) / (2.0f * sn) * th;
    float wy = (A[2] - A[8]) / (2.0f * sn) * th;
    float wz = (A[4] - A[1]) / (2.0f * sn) * th;
    if (fabsf(theta) < 1e-6f) { wx = 0.f; wy = 0.f; wz = 0.f; }
    float tx = A[3], ty = A[7], tz = A[11];
    float geod = sqrtf(tx * tx + ty * ty + tz * tz + wx * wx + wy * wy + wz * wz);
    float c = g_costs[b * M_HYP + m];
    tot[m] = c + geod;
    out[128 + b * M_HYP + m] = c;
  }
  __syncthreads();
  if (m == 0) {
    int best = 0;
    float bv = tot[0];
    for (int i = 1; i < M_HYP; i++)
      if (tot[i] < bv) { bv = tot[i]; best = i; }
    const float* Tb = g_Tcur + (size_t)(b * M_HYP + best) * 16;
#pragma unroll
    for (int i = 0; i < 16; i++) out[b * 16 + i] = Tb[i];
  }
}

// ---------------------------------------------------------------------------
// Host launch
// ---------------------------------------------------------------------------
extern "C" void kernel_launch(void* const* d_in, const int* in_sizes, int n_in,
                              void* d_out, int out_size)
{
  const float* T_pred = (const float*)d_in[0];
  const float* geo    = (const float*)d_in[1];
  const float* Kin    = (const float*)d_in[2];
  const float* q0 = (const float*)d_in[3];
  const float* q1 = (const float*)d_in[4];
  const float* q2 = (const float*)d_in[5];
  const float* r0 = (const float*)d_in[6];
  const float* r1 = (const float*)d_in[7];
  const float* r2 = (const float*)d_in[8];
  const float* u0 = (const float*)d_in[9];
  const float* u1 = (const float*)d_in[10];
  const float* u2 = (const float*)d_in[11];
  float* out = (float*)d_out;

  __nv_bfloat16 *D0p, *D1p, *D2p;
  cudaGetSymbolAddress((void**)&D0p, g_D0);
  cudaGetSymbolAddress((void**)&D1p, g_D1);
  cudaGetSymbolAddress((void**)&D2p, g_D2);

  unsigned hk0, hk1;
  threefry2x32(0u, 42u, 0u, 0u, &hk0, &hk1);

  // one prep launch: hypotheses + noise + all three transposed bf16 diffs
  int prep_blocks = B_SZ + 1 + T0_TILES + T1_TILES + T2_TILES;
  prep_kernel<<<prep_blocks, 256>>>(q0, r0, q1, r1, q2, r2, D0p, D1p, D2p,
                                    T_pred, hk0, hk1);

  const int iters[3] = { 2, 3, 4 };
  const int grid_res = B_SZ * M16 * PS;    // 1024 blocks
  int iter_idx = 0;
  for (int level = 0; level < 3; level++) {
    float scale = 1.0f / (4.0f / (float)(1 << level));
    float damping = (float)(0.001 * pow(0.5, (double)level));
    for (int it = 0; it < iters[level]; it++) {
      if (level == 0)
        residual_kernel<4><<<grid_res, 256>>>(D0p, u0, geo, Kin, C0, H0, W0, scale);
      else if (level == 1)
        residual_kernel<2><<<grid_res, 256>>>(D1p, u1, geo, Kin, C1, H1, W1, scale);
      else
        residual_kernel<1><<<grid_res, 256>>>(D2p, u2, geo, Kin, C2, H2, W2, scale);
      update_kernel<<<1, 128>>>(iter_idx, damping);
      iter_idx++;
    }
  }

  final_kernel<<<B_SZ, M_HYP>>>(T_pred, out);
  (void)in_sizes; (void)n_in; (void)out_size;
}

// round 8
// speedup vs baseline: 2.6114x; 1.4023x over previous
#include <cuda_runtime.h>
#include <cuda_bf16.h>
#include <math.h>

// ---------------------------------------------------------------------------
// Problem dimensions (fixed by the reference setup)
// ---------------------------------------------------------------------------
#define B_SZ   8
#define N_PTS  500
#define M_HYP  144
#define M16    16
#define PS     2           // point slices per (b,m): 250 points each
#define N_ITER 9

#define C0 128
#define H0 48
#define W0 64
#define C1 64
#define H1 96
#define W1 128
#define C2 32
#define H2 192
#define W2 256

// transpose tile counts (32x32 tiles)
#define T0_TILES ((H0*W0/32) * (C0/32) * B_SZ)   // 3072
#define T1_TILES ((H1*W1/32) * (C1/32) * B_SZ)   // 6144
#define T2_TILES ((H2*W2/32) * (C2/32) * B_SZ)   // 12288

// ---------------------------------------------------------------------------
// Scratch (__device__ globals — no allocation allowed). D stored as bf16.
// ---------------------------------------------------------------------------
__device__ __nv_bfloat16 g_D0[(size_t)B_SZ * H0 * W0 * C0];   // q0-r0, channel-last
__device__ __nv_bfloat16 g_D1[(size_t)B_SZ * H1 * W1 * C1];
__device__ __nv_bfloat16 g_D2[(size_t)B_SZ * H2 * W2 * C2];
__device__ float g_Tbuf[2][B_SZ * M_HYP * 16];      // double-buffered poses
__device__ float g_resacc[2][PS][B_SZ * M16];        // double-buffered partial residuals
__device__ float g_noise[N_ITER * B_SZ * M16 * 6];   // precomputed LM noise (m<16 only)

// ---------------------------------------------------------------------------
// Threefry-2x32 (exactly JAX's 20-round schedule; KAT-verified)
// ---------------------------------------------------------------------------
__host__ __device__ __forceinline__ void threefry2x32(
    unsigned k0, unsigned k1, unsigned x0, unsigned x1,
    unsigned* o0, unsigned* o1)
{
  unsigned ks2 = k0 ^ k1 ^ 0x1BD11BDAu;
#define TFR(r) { x0 += x1; x1 = (x1 << (r)) | (x1 >> (32 - (r))); x1 ^= x0; }
  x0 += k0;  x1 += k1;
  TFR(13) TFR(15) TFR(26) TFR(6)
  x0 += k1;  x1 += ks2 + 1u;
  TFR(17) TFR(29) TFR(16) TFR(24)
  x0 += ks2; x1 += k0 + 2u;
  TFR(13) TFR(15) TFR(26) TFR(6)
  x0 += k0;  x1 += k1 + 3u;
  TFR(17) TFR(29) TFR(16) TFR(24)
  x0 += k1;  x1 += ks2 + 4u;
  TFR(13) TFR(15) TFR(26) TFR(6)
  x0 += ks2; x1 += k0 + 5u;
#undef TFR
  *o0 = x0; *o1 = x1;
}

// Giles/XLA erfinv (same coefficients as XLA ErfInv32)
__device__ __forceinline__ float erfinv_f(float x)
{
  float w = -log1pf(-x * x);
  float p;
  if (w < 5.0f) {
    w = w - 2.5f;
    p = 2.81022636e-08f;
    p = fmaf(p, w, 3.43273939e-07f);
    p = fmaf(p, w, -3.5233877e-06f);
    p = fmaf(p, w, -4.39150654e-06f);
    p = fmaf(p, w, 0.00021858087f);
    p = fmaf(p, w, -0.00125372503f);
    p = fmaf(p, w, -0.00417768164f);
    p = fmaf(p, w, 0.246640727f);
    p = fmaf(p, w, 1.50140941f);
  } else {
    w = sqrtf(w) - 3.0f;
    p = -0.000200214257f;
    p = fmaf(p, w, 0.000100950558f);
    p = fmaf(p, w, 0.00134934322f);
    p = fmaf(p, w, -0.00367342844f);
    p = fmaf(p, w, 0.00573950773f);
    p = fmaf(p, w, -0.0076224613f);
    p = fmaf(p, w, 0.00943887047f);
    p = fmaf(p, w, 1.00167406f);
    p = fmaf(p, w, 2.83297682f);
  }
  return p * x;
}

__device__ __forceinline__ float bits_to_normal(unsigned bits)
{
  float u = __uint_as_float((bits >> 9) | 0x3f800000u) - 1.0f;
  const float lo = -0.99999994f;
  float v = fmaxf(lo, u * 2.0f + lo);
  return 1.41421356237f * erfinv_f(v);
}

// PARTITIONABLE threefry: (y0,y1) = threefry(key; 0, j); 32-bit draw = y0 ^ y1.
__device__ __forceinline__ float jax_normal_elem(unsigned k0, unsigned k1, unsigned j)
{
  unsigned y0, y1;
  threefry2x32(k0, k1, 0u, j, &y0, &y1);
  return bits_to_normal(y0 ^ y1);
}

// ---------------------------------------------------------------------------
// se3_exp (matches reference element-by-element)
// ---------------------------------------------------------------------------
__device__ __forceinline__ void mat3mul(const float* A, const float* Bm, float* Cm)
{
#pragma unroll
  for (int i = 0; i < 3; i++)
#pragma unroll
    for (int j = 0; j < 3; j++)
      Cm[i * 3 + j] = A[i * 3 + 0] * Bm[0 * 3 + j] + A[i * 3 + 1] * Bm[1 * 3 + j] + A[i * 3 + 2] * Bm[2 * 3 + j];
}

__device__ void se3_exp6(const float xi[6], float T[16])
{
  float tx = xi[0], ty = xi[1], tz = xi[2];
  float wx = xi[3], wy = xi[4], wz = xi[5];
  float theta = fmaxf(sqrtf(wx * wx + wy * wy + wz * wz), 1e-8f);
  float kx = wx / theta, ky = wy / theta, kz = wz / theta;
  float K[9] = { 0.f, -kz, ky,  kz, 0.f, -kx,  -ky, kx, 0.f };
  float KK[9];
  mat3mul(K, K, KK);
  float st = sinf(theta);
  float ct = 1.0f - cosf(theta);
  float a  = ct / theta;
  float bb = 1.0f - st / theta;
  float R[9], V[9];
#pragma unroll
  for (int i = 0; i < 9; i++) {
    float e = (i == 0 || i == 4 || i == 8) ? 1.0f : 0.0f;
    R[i] = e + st * K[i] + ct * KK[i];
    V[i] = e + a  * K[i] + bb * KK[i];
  }
  float tox = V[0] * tx + V[1] * ty + V[2] * tz;
  float toy = V[3] * tx + V[4] * ty + V[5] * tz;
  float toz = V[6] * tx + V[7] * ty + V[8] * tz;
  T[0] = R[0]; T[1] = R[1]; T[2]  = R[2]; T[3]  = tox;
  T[4] = R[3]; T[5] = R[4]; T[6]  = R[5]; T[7]  = toy;
  T[8] = R[6]; T[9] = R[7]; T[10] = R[8]; T[11] = toz;
  T[12] = 0.f; T[13] = 0.f; T[14] = 0.f; T[15] = 1.f;
}

// Apply LM delta for item bm (= b*16+m): T_out = se3_exp(step) @ T_in
__device__ __forceinline__ void apply_update(
    float Tm[16], int bm, int noise_iter, float damping, float res)
{
  const float* nz = g_noise + ((size_t)(noise_iter * (B_SZ * M16) + bm)) * 6;
  float s1 = -damping * res * 0.01f;
  float xi[6];
#pragma unroll
  for (int k = 0; k < 6; k++) xi[k] = s1 * nz[k];
  float D[16];
  se3_exp6(xi, D);
  float Told[16];
#pragma unroll
  for (int t = 0; t < 16; t++) Told[t] = Tm[t];
#pragma unroll
  for (int r = 0; r < 4; r++)
#pragma unroll
    for (int cc = 0; cc < 4; cc++)
      Tm[r * 4 + cc] = D[r * 4 + 0] * Told[0 * 4 + cc] + D[r * 4 + 1] * Told[1 * 4 + cc]
                     + D[r * 4 + 2] * Told[2 * 4 + cc] + D[r * 4 + 3] * Told[3 * 4 + cc];
}

// ---------------------------------------------------------------------------
// Transpose helper: one 32x32 tile of D = q - r, (B,C,HW) -> (B,HW,C), bf16
// ---------------------------------------------------------------------------
__device__ __forceinline__ void do_tile(
    const float* __restrict__ q, const float* __restrict__ r,
    __nv_bfloat16* __restrict__ Dt, int C, int HW,
    int b, int c0, int hw0, float* tile /* [32][33] */)
{
  const float* qb = q + (size_t)b * C * HW;
  const float* rb = r + (size_t)b * C * HW;
  __nv_bfloat16* Db = Dt + (size_t)b * HW * C;
  int tx = threadIdx.x & 31, ty = threadIdx.x >> 5;
#pragma unroll
  for (int i = ty; i < 32; i += 8) {
    int c = c0 + i, hw = hw0 + tx;
    tile[i * 33 + tx] = qb[(size_t)c * HW + hw] - rb[(size_t)c * HW + hw];
  }
  __syncthreads();
  int tid = threadIdx.x;
#pragma unroll
  for (int idx = tid; idx < 32 * 16; idx += 256) {
    int row = idx >> 4;
    int pr  = idx & 15;
    __nv_bfloat162 h = __floats2bfloat162_rn(tile[(2 * pr) * 33 + row],
                                             tile[(2 * pr + 1) * 33 + row]);
    *(__nv_bfloat162*)(Db + (size_t)(hw0 + row) * C + c0 + 2 * pr) = h;
  }
}

// ---------------------------------------------------------------------------
// prep kernel: blocks [0,8) = hypotheses (both T buffers); block 8 = noise;
// rest = transpose tiles of L0/L1/L2
// ---------------------------------------------------------------------------
__global__ __launch_bounds__(256) void prep_kernel(
    const float* __restrict__ q0, const float* __restrict__ r0,
    const float* __restrict__ q1, const float* __restrict__ r1,
    const float* __restrict__ q2, const float* __restrict__ r2,
    __nv_bfloat16* __restrict__ D0, __nv_bfloat16* __restrict__ D1,
    __nv_bfloat16* __restrict__ D2,
    const float* __restrict__ Tpred, unsigned k0, unsigned k1)
{
  __shared__ float tile[32 * 33];
  int blk = blockIdx.x;
  if (blk < B_SZ) {
    int m = threadIdx.x;
    int b = blk;
    if (m >= M_HYP) return;
    float xi[6];
#pragma unroll
    for (int k = 0; k < 3; k++)
      xi[k] = jax_normal_elem(k0, k1, (unsigned)(m * 3 + k));
    int pi = m / 12, yj = m % 12;
    const float D2R = (float)(3.14159265358979323846 / 180.0);
    xi[3] = 0.0f;
    xi[4] = (-11.0f + 2.0f * (float)pi) * D2R;
    xi[5] = (-11.0f + 2.0f * (float)yj) * D2R;
    float dT[16];
    se3_exp6(xi, dT);
    const float* P = Tpred + b * 16;
    size_t off = (size_t)(b * M_HYP + m) * 16;
#pragma unroll
    for (int i = 0; i < 4; i++)
#pragma unroll
      for (int j = 0; j < 4; j++) {
        float v = dT[i * 4 + 0] * P[0 * 4 + j] + dT[i * 4 + 1] * P[1 * 4 + j]
                + dT[i * 4 + 2] * P[2 * 4 + j] + dT[i * 4 + 3] * P[3 * 4 + j];
        g_Tbuf[0][off + i * 4 + j] = v;
        g_Tbuf[1][off + i * 4 + j] = v;
      }
    return;
  }
  blk -= B_SZ;
  if (blk == 0) {
    // noise precompute for all 9 iterations (m<16 only)
    const int LI[N_ITER] = {100, 101, 110, 111, 112, 120, 121, 122, 123};
    int tid = threadIdx.x;
    for (int it = 0; it < N_ITER; it++) {
      unsigned ik0, ik1;
      threefry2x32(0u, 42u, 0u, (unsigned)LI[it], &ik0, &ik1);
      for (int idx = tid; idx < B_SZ * M16 * 6; idx += 256) {
        int i = idx / 6, k = idx % 6;
        int b = i >> 4, m = i & 15;
        unsigned j = (unsigned)((b * M_HYP + m) * 6 + k);
        g_noise[it * (B_SZ * M16 * 6) + idx] = jax_normal_elem(ik0, ik1, j);
      }
    }
    return;
  }
  blk -= 1;
  if (blk < T0_TILES) {
    const int HWT = H0 * W0 / 32, CT = C0 / 32;
    int b = blk / (HWT * CT);
    int rem = blk % (HWT * CT);
    int c0 = (rem / HWT) * 32, hw0 = (rem % HWT) * 32;
    do_tile(q0, r0, D0, C0, H0 * W0, b, c0, hw0, tile);
    return;
  }
  blk -= T0_TILES;
  if (blk < T1_TILES) {
    const int HWT = H1 * W1 / 32, CT = C1 / 32;
    int b = blk / (HWT * CT);
    int rem = blk % (HWT * CT);
    int c0 = (rem / HWT) * 32, hw0 = (rem % HWT) * 32;
    do_tile(q1, r1, D1, C1, H1 * W1, b, c0, hw0, tile);
    return;
  }
  blk -= T1_TILES;
  {
    const int HWT = H2 * W2 / 32;
    int b = blk / HWT;
    int hw0 = (blk % HWT) * 32;
    do_tile(q2, r2, D2, C2, H2 * W2, b, 0, hw0, tile);
  }
}

// ---------------------------------------------------------------------------
// Residual kernel with fused per-bm LM update prologue.
// grid = B*16*PS = 256 blocks, 256 threads (8 warps).
// Each warp: lane l owns point idxInSlice = w + 8*l (SIMD projections),
// then an inner loop broadcasts each point and lanes cover channels.
// Units per pixel = 32 load-vectors for ALL levels (C/vecwidth = 32).
// ---------------------------------------------------------------------------
template <int CPL>
__global__ __launch_bounds__(256) void residual_kernel(
    const __nv_bfloat16* __restrict__ Dt, const float* __restrict__ Umap,
    const float* __restrict__ geo, const float* __restrict__ Kin,
    int C, int H, int W, float scale, int iter, float damping_prev)
{
  int bm    = blockIdx.x >> 1;
  int slice = blockIdx.x & 1;
  int b = bm >> 4, m = bm & 15;
  int lane = threadIdx.x & 31, w = threadIdx.x >> 5;
  int rp = (iter + 1) & 1, wp = iter & 1;

  // ---- prologue: compute T_iter for this bm (redundant across threads) ----
  float Tm[16];
  {
    const float* Tsrc = g_Tbuf[rp] + (size_t)(b * M_HYP + m) * 16;
#pragma unroll
    for (int i = 0; i < 16; i++) Tm[i] = Tsrc[i];
    if (iter > 0) {
      float res = (g_resacc[rp][0][bm] + g_resacc[rp][1][bm]) * (1.0f / N_PTS);
      apply_update(Tm, bm, iter - 1, damping_prev, res);
      if (threadIdx.x < 16)
        g_Tbuf[wp][(size_t)(b * M_HYP + m) * 16 + threadIdx.x] = Tm[threadIdx.x];
    }
  }

  float T00 = Tm[0], T01 = Tm[1], T02 = Tm[2],  T03 = Tm[3];
  float T10 = Tm[4], T11 = Tm[5], T12 = Tm[6],  T13 = Tm[7];
  float T20 = Tm[8], T21 = Tm[9], T22 = Tm[10], T23 = Tm[11];
  float fx = __ldg(Kin + b * 9 + 0) * scale, cx = __ldg(Kin + b * 9 + 2) * scale;
  float fy = __ldg(Kin + b * 9 + 4) * scale, cy = __ldg(Kin + b * 9 + 5) * scale;
  const __nv_bfloat16* Db = Dt + (size_t)b * H * W * C;
  const float* Ub = Umap + (size_t)b * H * W;
  const float* G  = geo + (size_t)b * N_PTS * 3;

  // ---- per-lane projection of its own point ----
  float Wm1 = (float)(W - 1), Hm1 = (float)(H - 1);
  int idxS = w + 8 * lane;                       // 0..255
  int n = slice * 250 + (idxS < 250 ? idxS : 249);
  int o00, o01, o10, o11;
  float w00, w01, w10, w11, us;
  {
    float X = __ldg(G + n * 3 + 0);
    float Y = __ldg(G + n * 3 + 1);
    float Z = __ldg(G + n * 3 + 2);
    float px = T00 * X + T01 * Y + T02 * Z + T03;
    float py = T10 * X + T11 * Y + T12 * Z + T13;
    float pz = T20 * X + T21 * Y + T22 * Z + T23;
    float z  = fmaxf(pz, 1e-6f);
    float u  = fx * (px / z) + cx;
    float v  = fy * (py / z) + cy;
    float gx = 2.0f * u / Wm1 - 1.0f;
    float gy = 2.0f * v / Hm1 - 1.0f;
    float xs = fminf(fmaxf(((gx + 1.0f) * (float)W - 1.0f) * 0.5f, 0.0f), Wm1);
    float ys = fminf(fmaxf(((gy + 1.0f) * (float)H - 1.0f) * 0.5f, 0.0f), Hm1);
    float x0f = floorf(xs), y0f = floorf(ys);
    float x1f = fminf(x0f + 1.0f, Wm1), y1f = fminf(y0f + 1.0f, Hm1);
    float wx = xs - x0f, wy = ys - y0f;
    int x0 = (int)x0f, x1 = (int)x1f, y0 = (int)y0f, y1 = (int)y1f;
    w00 = (1.0f - wx) * (1.0f - wy); w01 = wx * (1.0f - wy);
    w10 = (1.0f - wx) * wy;          w11 = wx * wy;
    int r0 = y0 * W, r1 = y1 * W;
    us = w00 * __ldg(Ub + r0 + x0) + w01 * __ldg(Ub + r0 + x1)
       + w10 * __ldg(Ub + r1 + x0) + w11 * __ldg(Ub + r1 + x1);
    o00 = (r0 + x0) * 32; o01 = (r0 + x1) * 32;
    o10 = (r1 + x0) * 32; o11 = (r1 + x1) * 32;
  }

  int vc = (257 - w) >> 3;                       // valid points in this warp
  float wacc = 0.0f;
  for (int p = 0; p < vc; p++) {
    int   a00 = __shfl_sync(0xffffffffu, o00, p);
    int   a01 = __shfl_sync(0xffffffffu, o01, p);
    int   a10 = __shfl_sync(0xffffffffu, o10, p);
    int   a11 = __shfl_sync(0xffffffffu, o11, p);
    float pw00 = __shfl_sync(0xffffffffu, w00, p);
    float pw01 = __shfl_sync(0xffffffffu, w01, p);
    float pw10 = __shfl_sync(0xffffffffu, w10, p);
    float pw11 = __shfl_sync(0xffffffffu, w11, p);
    float pus  = __shfl_sync(0xffffffffu, us,  p);

    float spt;
    if constexpr (CPL == 4) {
      const uint2* base = (const uint2*)Db;
      uint2 va = __ldg(base + a00 + lane);
      uint2 vb = __ldg(base + a01 + lane);
      uint2 vcc = __ldg(base + a10 + lane);
      uint2 vd = __ldg(base + a11 + lane);
      float2 a0 = __bfloat1622float2(*(__nv_bfloat162*)&va.x);
      float2 a1 = __bfloat1622float2(*(__nv_bfloat162*)&va.y);
      float2 b0 = __bfloat1622float2(*(__nv_bfloat162*)&vb.x);
      float2 b1 = __bfloat1622float2(*(__nv_bfloat162*)&vb.y);
      float2 c0v = __bfloat1622float2(*(__nv_bfloat162*)&vcc.x);
      float2 c1 = __bfloat1622float2(*(__nv_bfloat162*)&vcc.y);
      float2 d0v = __bfloat1622float2(*(__nv_bfloat162*)&vd.x);
      float2 d1 = __bfloat1622float2(*(__nv_bfloat162*)&vd.y);
      float e0 = pw00 * a0.x; e0 = fmaf(pw01, b0.x, e0); e0 = fmaf(pw10, c0v.x, e0); e0 = fmaf(pw11, d0v.x, e0);
      float e1 = pw00 * a0.y; e1 = fmaf(pw01, b0.y, e1); e1 = fmaf(pw10, c0v.y, e1); e1 = fmaf(pw11, d0v.y, e1);
      float e2 = pw00 * a1.x; e2 = fmaf(pw01, b1.x, e2); e2 = fmaf(pw10, c1.x, e2); e2 = fmaf(pw11, d1.x, e2);
      float e3 = pw00 * a1.y; e3 = fmaf(pw01, b1.y, e3); e3 = fmaf(pw10, c1.y, e3); e3 = fmaf(pw11, d1.y, e3);
      spt = e0 * e0 + e1 * e1 + e2 * e2 + e3 * e3;
    } else if constexpr (CPL == 2) {
      const unsigned* base = (const unsigned*)Db;
      unsigned va = __ldg(base + a00 + lane);
      unsigned vb = __ldg(base + a01 + lane);
      unsigned vcc = __ldg(base + a10 + lane);
      unsigned vd = __ldg(base + a11 + lane);
      float2 a = __bfloat1622float2(*(__nv_bfloat162*)&va);
      float2 bq = __bfloat1622float2(*(__nv_bfloat162*)&vb);
      float2 c = __bfloat1622float2(*(__nv_bfloat162*)&vcc);
      float2 d = __bfloat1622float2(*(__nv_bfloat162*)&vd);
      float e0 = pw00 * a.x; e0 = fmaf(pw01, bq.x, e0); e0 = fmaf(pw10, c.x, e0); e0 = fmaf(pw11, d.x, e0);
      float e1 = pw00 * a.y; e1 = fmaf(pw01, bq.y, e1); e1 = fmaf(pw10, c.y, e1); e1 = fmaf(pw11, d.y, e1);
      spt = e0 * e0 + e1 * e1;
    } else {
      float a  = __bfloat162float(__ldg(Db + a00 + lane));
      float bq = __bfloat162float(__ldg(Db + a01 + lane));
      float c  = __bfloat162float(__ldg(Db + a10 + lane));
      float d  = __bfloat162float(__ldg(Db + a11 + lane));
      float e0 = pw00 * a; e0 = fmaf(pw01, bq, e0); e0 = fmaf(pw10, c, e0); e0 = fmaf(pw11, d, e0);
      spt = e0 * e0;
    }
    wacc = fmaf(pus, spt, wacc);
  }
#pragma unroll
  for (int o = 16; o; o >>= 1) wacc += __shfl_xor_sync(0xffffffffu, wacc, o);
  __shared__ float wpar[8];
  if (lane == 0) wpar[w] = wacc;
  __syncthreads();
  if (threadIdx.x == 0) {
    float s = 0.0f;
#pragma unroll
    for (int ww = 0; ww < 8; ww++) s += wpar[ww];
    g_resacc[wp][slice][bm] = s;
  }
}

// ---------------------------------------------------------------------------
// final kernel: applies the 9th LM update, then geodesic + argmin + output.
// grid = B blocks x 144 threads. After iter 8: T_8 in g_Tbuf[0], res_8 in
// g_resacc[0].
// ---------------------------------------------------------------------------
__global__ void final_kernel(const float* __restrict__ Tpred, float* __restrict__ out,
                             float damping_last)
{
  int b = blockIdx.x;
  int m = threadIdx.x;
  __shared__ float tot[M_HYP];
  if (m < M_HYP) {
    float Tc[16];
    const float* Tsrc = g_Tbuf[0] + (size_t)(b * M_HYP + m) * 16;
#pragma unroll
    for (int i = 0; i < 16; i++) Tc[i] = Tsrc[i];
    float c = 0.0f;
    if (m < M16) {
      int bm = b * M16 + m;
      c = (g_resacc[0][0][bm] + g_resacc[0][1][bm]) * (1.0f / N_PTS);
      apply_update(Tc, bm, 8, damping_last, c);
    }
    const float* P = Tpred + b * 16;
    float Ri[9] = { P[0], P[4], P[8],  P[1], P[5], P[9],  P[2], P[6], P[10] };
    float tix = -(Ri[0] * P[3] + Ri[1] * P[7] + Ri[2] * P[11]);
    float tiy = -(Ri[3] * P[3] + Ri[4] * P[7] + Ri[5] * P[11]);
    float tiz = -(Ri[6] * P[3] + Ri[7] * P[7] + Ri[8] * P[11]);
    float Ti[16] = { Ri[0], Ri[1], Ri[2], tix,
                     Ri[3], Ri[4], Ri[5], tiy,
                     Ri[6], Ri[7], Ri[8], tiz,
                     0.f, 0.f, 0.f, 1.f };
    float A[16];
#pragma unroll
    for (int i = 0; i < 4; i++)
#pragma unroll
      for (int j = 0; j < 4; j++)
        A[i * 4 + j] = Tc[i * 4 + 0] * Ti[0 * 4 + j] + Tc[i * 4 + 1] * Ti[1 * 4 + j]
                     + Tc[i * 4 + 2] * Ti[2 * 4 + j] + Tc[i * 4 + 3] * Ti[3 * 4 + j];
    float cos_a = (A[0] + A[5] + A[10] - 1.0f) * 0.5f;
    const float CL = (float)(1.0 - 1e-7);
    cos_a = fminf(fmaxf(cos_a, -CL), CL);
    float theta = acosf(cos_a);
    float th = fmaxf(theta, 1e-8f);
    float sn = fmaxf(sinf(th), 1e-8f);
    float wx = (A[9] - A[6]) / (2.0f * sn) * th;
    float wy = (A[2] - A[8]) / (2.0f * sn) * th;
    float wz = (A[4] - A[1]) / (2.0f * sn) * th;
    if (fabsf(theta) < 1e-6f) { wx = 0.f; wy = 0.f; wz = 0.f; }
    float tx = A[3], ty = A[7], tz = A[11];
    float geod = sqrtf(tx * tx + ty * ty + tz * tz + wx * wx + wy * wy + wz * wz);
    tot[m] = c + geod;
    out[128 + b * M_HYP + m] = c;
    // stash updated pose for the argmin winner (shared not enough: reuse gmem)
    float* Tdst = g_Tbuf[1] + (size_t)(b * M_HYP + m) * 16;
#pragma unroll
    for (int i = 0; i < 16; i++) Tdst[i] = Tc[i];
  }
  __syncthreads();
  if (m == 0) {
    int best = 0;
    float bv = tot[0];
    for (int i = 1; i < M_HYP; i++)
      if (tot[i] < bv) { bv = tot[i]; best = i; }
    const float* Tb = g_Tbuf[1] + (size_t)(b * M_HYP + best) * 16;
#pragma unroll
    for (int i = 0; i < 16; i++) out[b * 16 + i] = Tb[i];
  }
}

// ---------------------------------------------------------------------------
// Host launch
// ---------------------------------------------------------------------------
extern "C" void kernel_launch(void* const* d_in, const int* in_sizes, int n_in,
                              void* d_out, int out_size)
{
  const float* T_pred = (const float*)d_in[0];
  const float* geo    = (const float*)d_in[1];
  const float* Kin    = (const float*)d_in[2];
  const float* q0 = (const float*)d_in[3];
  const float* q1 = (const float*)d_in[4];
  const float* q2 = (const float*)d_in[5];
  const float* r0 = (const float*)d_in[6];
  const float* r1 = (const float*)d_in[7];
  const float* r2 = (const float*)d_in[8];
  const float* u0 = (const float*)d_in[9];
  const float* u1 = (const float*)d_in[10];
  const float* u2 = (const float*)d_in[11];
  float* out = (float*)d_out;

  __nv_bfloat16 *D0p, *D1p, *D2p;
  cudaGetSymbolAddress((void**)&D0p, g_D0);
  cudaGetSymbolAddress((void**)&D1p, g_D1);
  cudaGetSymbolAddress((void**)&D2p, g_D2);

  unsigned hk0, hk1;
  threefry2x32(0u, 42u, 0u, 0u, &hk0, &hk1);

  int prep_blocks = B_SZ + 1 + T0_TILES + T1_TILES + T2_TILES;
  prep_kernel<<<prep_blocks, 256>>>(q0, r0, q1, r1, q2, r2, D0p, D1p, D2p,
                                    T_pred, hk0, hk1);

  const int   lvl[N_ITER]  = {0, 0, 1, 1, 1, 2, 2, 2, 2};
  const float damp[3]      = {0.001f, 0.0005f, 0.00025f};
  const int   grid_res = B_SZ * M16 * PS;    // 256 blocks
  for (int k = 0; k < N_ITER; k++) {
    int level = lvl[k];
    float scale = 1.0f / (4.0f / (float)(1 << level));
    float dprev = (k > 0) ? damp[lvl[k - 1]] : 0.0f;
    if (level == 0)
      residual_kernel<4><<<grid_res, 256>>>(D0p, u0, geo, Kin, C0, H0, W0, scale, k, dprev);
    else if (level == 1)
      residual_kernel<2><<<grid_res, 256>>>(D1p, u1, geo, Kin, C1, H1, W1, scale, k, dprev);
    else
      residual_kernel<1><<<grid_res, 256>>>(D2p, u2, geo, Kin, C2, H2, W2, scale, k, dprev);
  }

  final_kernel<<<B_SZ, M_HYP>>>(T_pred, out, damp[2]);
  (void)in_sizes; (void)n_in; (void)out_size;
}

// round 9
// speedup vs baseline: 2.6740x; 1.0240x over previous
#include <cuda_runtime.h>
#include <cuda_bf16.h>
#include <math.h>

// ---------------------------------------------------------------------------
// Problem dimensions (fixed by the reference setup)
// ---------------------------------------------------------------------------
#define B_SZ   8
#define N_PTS  500
#define M_HYP  144
#define M16    16
#define PS     8           // point slices per (b,m): 63 points each (last: 59)
#define N_ITER 9

#define C0 128
#define H0 48
#define W0 64
#define C1 64
#define H1 96
#define W1 128
#define C2 32
#define H2 192
#define W2 256

// transpose tile counts (32x32 tiles)
#define T0_TILES ((H0*W0/32) * (C0/32) * B_SZ)   // 3072
#define T1_TILES ((H1*W1/32) * (C1/32) * B_SZ)   // 6144
#define T2_TILES ((H2*W2/32) * (C2/32) * B_SZ)   // 12288

// ---------------------------------------------------------------------------
// Scratch (__device__ globals — no allocation allowed). D stored as bf16.
// ---------------------------------------------------------------------------
__device__ __nv_bfloat16 g_D0[(size_t)B_SZ * H0 * W0 * C0];   // q0-r0, channel-last
__device__ __nv_bfloat16 g_D1[(size_t)B_SZ * H1 * W1 * C1];
__device__ __nv_bfloat16 g_D2[(size_t)B_SZ * H2 * W2 * C2];
__device__ float g_Tbuf[2][B_SZ * M_HYP * 16];       // double-buffered poses
__device__ float g_resacc[2][PS][B_SZ * M16];         // double-buffered partial residuals
__device__ float g_noise[N_ITER * B_SZ * M16 * 6];    // precomputed LM noise (m<16 only)

// ---------------------------------------------------------------------------
// Threefry-2x32 (exactly JAX's 20-round schedule; KAT-verified)
// ---------------------------------------------------------------------------
__host__ __device__ __forceinline__ void threefry2x32(
    unsigned k0, unsigned k1, unsigned x0, unsigned x1,
    unsigned* o0, unsigned* o1)
{
  unsigned ks2 = k0 ^ k1 ^ 0x1BD11BDAu;
#define TFR(r) { x0 += x1; x1 = (x1 << (r)) | (x1 >> (32 - (r))); x1 ^= x0; }
  x0 += k0;  x1 += k1;
  TFR(13) TFR(15) TFR(26) TFR(6)
  x0 += k1;  x1 += ks2 + 1u;
  TFR(17) TFR(29) TFR(16) TFR(24)
  x0 += ks2; x1 += k0 + 2u;
  TFR(13) TFR(15) TFR(26) TFR(6)
  x0 += k0;  x1 += k1 + 3u;
  TFR(17) TFR(29) TFR(16) TFR(24)
  x0 += k1;  x1 += ks2 + 4u;
  TFR(13) TFR(15) TFR(26) TFR(6)
  x0 += ks2; x1 += k0 + 5u;
#undef TFR
  *o0 = x0; *o1 = x1;
}

// Giles/XLA erfinv (same coefficients as XLA ErfInv32)
__device__ __forceinline__ float erfinv_f(float x)
{
  float w = -log1pf(-x * x);
  float p;
  if (w < 5.0f) {
    w = w - 2.5f;
    p = 2.81022636e-08f;
    p = fmaf(p, w, 3.43273939e-07f);
    p = fmaf(p, w, -3.5233877e-06f);
    p = fmaf(p, w, -4.39150654e-06f);
    p = fmaf(p, w, 0.00021858087f);
    p = fmaf(p, w, -0.00125372503f);
    p = fmaf(p, w, -0.00417768164f);
    p = fmaf(p, w, 0.246640727f);
    p = fmaf(p, w, 1.50140941f);
  } else {
    w = sqrtf(w) - 3.0f;
    p = -0.000200214257f;
    p = fmaf(p, w, 0.000100950558f);
    p = fmaf(p, w, 0.00134934322f);
    p = fmaf(p, w, -0.00367342844f);
    p = fmaf(p, w, 0.00573950773f);
    p = fmaf(p, w, -0.0076224613f);
    p = fmaf(p, w, 0.00943887047f);
    p = fmaf(p, w, 1.00167406f);
    p = fmaf(p, w, 2.83297682f);
  }
  return p * x;
}

__device__ __forceinline__ float bits_to_normal(unsigned bits)
{
  float u = __uint_as_float((bits >> 9) | 0x3f800000u) - 1.0f;
  const float lo = -0.99999994f;
  float v = fmaxf(lo, u * 2.0f + lo);
  return 1.41421356237f * erfinv_f(v);
}

// PARTITIONABLE threefry: (y0,y1) = threefry(key; 0, j); 32-bit draw = y0 ^ y1.
__device__ __forceinline__ float jax_normal_elem(unsigned k0, unsigned k1, unsigned j)
{
  unsigned y0, y1;
  threefry2x32(k0, k1, 0u, j, &y0, &y1);
  return bits_to_normal(y0 ^ y1);
}

// ---------------------------------------------------------------------------
// se3_exp (matches reference element-by-element)
// ---------------------------------------------------------------------------
__device__ __forceinline__ void mat3mul(const float* A, const float* Bm, float* Cm)
{
#pragma unroll
  for (int i = 0; i < 3; i++)
#pragma unroll
    for (int j = 0; j < 3; j++)
      Cm[i * 3 + j] = A[i * 3 + 0] * Bm[0 * 3 + j] + A[i * 3 + 1] * Bm[1 * 3 + j] + A[i * 3 + 2] * Bm[2 * 3 + j];
}

__device__ void se3_exp6(const float xi[6], float T[16])
{
  float tx = xi[0], ty = xi[1], tz = xi[2];
  float wx = xi[3], wy = xi[4], wz = xi[5];
  float theta = fmaxf(sqrtf(wx * wx + wy * wy + wz * wz), 1e-8f);
  float kx = wx / theta, ky = wy / theta, kz = wz / theta;
  float K[9] = { 0.f, -kz, ky,  kz, 0.f, -kx,  -ky, kx, 0.f };
  float KK[9];
  mat3mul(K, K, KK);
  float st = sinf(theta);
  float ct = 1.0f - cosf(theta);
  float a  = ct / theta;
  float bb = 1.0f - st / theta;
  float R[9], V[9];
#pragma unroll
  for (int i = 0; i < 9; i++) {
    float e = (i == 0 || i == 4 || i == 8) ? 1.0f : 0.0f;
    R[i] = e + st * K[i] + ct * KK[i];
    V[i] = e + a  * K[i] + bb * KK[i];
  }
  float tox = V[0] * tx + V[1] * ty + V[2] * tz;
  float toy = V[3] * tx + V[4] * ty + V[5] * tz;
  float toz = V[6] * tx + V[7] * ty + V[8] * tz;
  T[0] = R[0]; T[1] = R[1]; T[2]  = R[2]; T[3]  = tox;
  T[4] = R[3]; T[5] = R[4]; T[6]  = R[5]; T[7]  = toy;
  T[8] = R[6]; T[9] = R[7]; T[10] = R[8]; T[11] = toz;
  T[12] = 0.f; T[13] = 0.f; T[14] = 0.f; T[15] = 1.f;
}

// Apply LM delta for item bm (= b*16+m): T_out = se3_exp(step) @ T_in
__device__ __forceinline__ void apply_update(
    float Tm[16], int bm, int noise_iter, float damping, float res)
{
  const float* nz = g_noise + ((size_t)(noise_iter * (B_SZ * M16) + bm)) * 6;
  float s1 = -damping * res * 0.01f;
  float xi[6];
#pragma unroll
  for (int k = 0; k < 6; k++) xi[k] = s1 * nz[k];
  float D[16];
  se3_exp6(xi, D);
  float Told[16];
#pragma unroll
  for (int t = 0; t < 16; t++) Told[t] = Tm[t];
#pragma unroll
  for (int r = 0; r < 4; r++)
#pragma unroll
    for (int cc = 0; cc < 4; cc++)
      Tm[r * 4 + cc] = D[r * 4 + 0] * Told[0 * 4 + cc] + D[r * 4 + 1] * Told[1 * 4 + cc]
                     + D[r * 4 + 2] * Told[2 * 4 + cc] + D[r * 4 + 3] * Told[3 * 4 + cc];
}

// ---------------------------------------------------------------------------
// Transpose helper: one 32x32 tile of D = q - r, (B,C,HW) -> (B,HW,C), bf16
// ---------------------------------------------------------------------------
__device__ __forceinline__ void do_tile(
    const float* __restrict__ q, const float* __restrict__ r,
    __nv_bfloat16* __restrict__ Dt, int C, int HW,
    int b, int c0, int hw0, float* tile /* [32][33] */)
{
  const float* qb = q + (size_t)b * C * HW;
  const float* rb = r + (size_t)b * C * HW;
  __nv_bfloat16* Db = Dt + (size_t)b * HW * C;
  int tx = threadIdx.x & 31, ty = threadIdx.x >> 5;
#pragma unroll
  for (int i = ty; i < 32; i += 8) {
    int c = c0 + i, hw = hw0 + tx;
    tile[i * 33 + tx] = qb[(size_t)c * HW + hw] - rb[(size_t)c * HW + hw];
  }
  __syncthreads();
  int tid = threadIdx.x;
#pragma unroll
  for (int idx = tid; idx < 32 * 16; idx += 256) {
    int row = idx >> 4;
    int pr  = idx & 15;
    __nv_bfloat162 h = __floats2bfloat162_rn(tile[(2 * pr) * 33 + row],
                                             tile[(2 * pr + 1) * 33 + row]);
    *(__nv_bfloat162*)(Db + (size_t)(hw0 + row) * C + c0 + 2 * pr) = h;
  }
}

// ---------------------------------------------------------------------------
// prep kernel: blocks [0,8) = hypotheses (both T buffers); block 8 = noise;
// rest = transpose tiles of L0/L1/L2
// ---------------------------------------------------------------------------
__global__ __launch_bounds__(256) void prep_kernel(
    const float* __restrict__ q0, const float* __restrict__ r0,
    const float* __restrict__ q1, const float* __restrict__ r1,
    const float* __restrict__ q2, const float* __restrict__ r2,
    __nv_bfloat16* __restrict__ D0, __nv_bfloat16* __restrict__ D1,
    __nv_bfloat16* __restrict__ D2,
    const float* __restrict__ Tpred, unsigned k0, unsigned k1)
{
  __shared__ float tile[32 * 33];
  int blk = blockIdx.x;
  if (blk < B_SZ) {
    int m = threadIdx.x;
    int b = blk;
    if (m >= M_HYP) return;
    float xi[6];
#pragma unroll
    for (int k = 0; k < 3; k++)
      xi[k] = jax_normal_elem(k0, k1, (unsigned)(m * 3 + k));
    int pi = m / 12, yj = m % 12;
    const float D2R = (float)(3.14159265358979323846 / 180.0);
    xi[3] = 0.0f;
    xi[4] = (-11.0f + 2.0f * (float)pi) * D2R;
    xi[5] = (-11.0f + 2.0f * (float)yj) * D2R;
    float dT[16];
    se3_exp6(xi, dT);
    const float* P = Tpred + b * 16;
    size_t off = (size_t)(b * M_HYP + m) * 16;
#pragma unroll
    for (int i = 0; i < 4; i++)
#pragma unroll
      for (int j = 0; j < 4; j++) {
        float v = dT[i * 4 + 0] * P[0 * 4 + j] + dT[i * 4 + 1] * P[1 * 4 + j]
                + dT[i * 4 + 2] * P[2 * 4 + j] + dT[i * 4 + 3] * P[3 * 4 + j];
        g_Tbuf[0][off + i * 4 + j] = v;
        g_Tbuf[1][off + i * 4 + j] = v;
      }
    return;
  }
  blk -= B_SZ;
  if (blk == 0) {
    const int LI[N_ITER] = {100, 101, 110, 111, 112, 120, 121, 122, 123};
    int tid = threadIdx.x;
    for (int it = 0; it < N_ITER; it++) {
      unsigned ik0, ik1;
      threefry2x32(0u, 42u, 0u, (unsigned)LI[it], &ik0, &ik1);
      for (int idx = tid; idx < B_SZ * M16 * 6; idx += 256) {
        int i = idx / 6, k = idx % 6;
        int b = i >> 4, m = i & 15;
        unsigned j = (unsigned)((b * M_HYP + m) * 6 + k);
        g_noise[it * (B_SZ * M16 * 6) + idx] = jax_normal_elem(ik0, ik1, j);
      }
    }
    return;
  }
  blk -= 1;
  if (blk < T0_TILES) {
    const int HWT = H0 * W0 / 32, CT = C0 / 32;
    int b = blk / (HWT * CT);
    int rem = blk % (HWT * CT);
    int c0 = (rem / HWT) * 32, hw0 = (rem % HWT) * 32;
    do_tile(q0, r0, D0, C0, H0 * W0, b, c0, hw0, tile);
    return;
  }
  blk -= T0_TILES;
  if (blk < T1_TILES) {
    const int HWT = H1 * W1 / 32, CT = C1 / 32;
    int b = blk / (HWT * CT);
    int rem = blk % (HWT * CT);
    int c0 = (rem / HWT) * 32, hw0 = (rem % HWT) * 32;
    do_tile(q1, r1, D1, C1, H1 * W1, b, c0, hw0, tile);
    return;
  }
  blk -= T1_TILES;
  {
    const int HWT = H2 * W2 / 32;
    int b = blk / HWT;
    int hw0 = (blk % HWT) * 32;
    do_tile(q2, r2, D2, C2, H2 * W2, b, 0, hw0, tile);
  }
}

// ---------------------------------------------------------------------------
// Residual kernel with fused per-bm LM update prologue.
// grid = B*16*PS = 1024 blocks, 256 threads (8 warps).
// Warp w owns points n = slice*63 + w + 8*p (p = 0..vc-1, vc <= 8).
// Lane l (l<8) projects point p=l; then channel loop broadcasts each point
// with a 1-deep software prefetch pipeline.
// ---------------------------------------------------------------------------
template <int CPL>
__global__ __launch_bounds__(256) void residual_kernel(
    const __nv_bfloat16* __restrict__ Dt, const float* __restrict__ Umap,
    const float* __restrict__ geo, const float* __restrict__ Kin,
    int C, int H, int W, float scale, int iter, float damping_prev)
{
  int bm    = blockIdx.x >> 3;
  int slice = blockIdx.x & 7;
  int b = bm >> 4, m = bm & 15;
  int lane = threadIdx.x & 31, w = threadIdx.x >> 5;
  int rp = (iter + 1) & 1, wpar_ = iter & 1;

  // ---- prologue: compute T_iter for this bm (redundant across threads) ----
  float Tm[16];
  {
    const float* Tsrc = g_Tbuf[rp] + (size_t)(b * M_HYP + m) * 16;
#pragma unroll
    for (int i = 0; i < 16; i++) Tm[i] = Tsrc[i];
    if (iter > 0) {
      float rs = 0.0f;
#pragma unroll
      for (int p = 0; p < PS; p++) rs += g_resacc[rp][p][bm];
      float res = rs * (1.0f / N_PTS);
      apply_update(Tm, bm, iter - 1, damping_prev, res);
      if (threadIdx.x < 16 && slice == 0)
        g_Tbuf[wpar_][(size_t)(b * M_HYP + m) * 16 + threadIdx.x] = Tm[threadIdx.x];
    }
  }

  float T00 = Tm[0], T01 = Tm[1], T02 = Tm[2],  T03 = Tm[3];
  float T10 = Tm[4], T11 = Tm[5], T12 = Tm[6],  T13 = Tm[7];
  float T20 = Tm[8], T21 = Tm[9], T22 = Tm[10], T23 = Tm[11];
  float fx = __ldg(Kin + b * 9 + 0) * scale, cx = __ldg(Kin + b * 9 + 2) * scale;
  float fy = __ldg(Kin + b * 9 + 4) * scale, cy = __ldg(Kin + b * 9 + 5) * scale;
  const __nv_bfloat16* Db = Dt + (size_t)b * H * W * C;
  const float* Ub = Umap + (size_t)b * H * W;
  const float* G  = geo + (size_t)b * N_PTS * 3;

  // ---- projection: lane l projects point slice*63 + w + 8*l ----
  float Wm1 = (float)(W - 1), Hm1 = (float)(H - 1);
  int nbeg = slice * 63 + w;
  int nend = min(N_PTS, slice * 63 + 63);
  int vc = (nend - nbeg + 7) >> 3;               // 1..8 points for this warp
  int n = min(nbeg + 8 * (lane & 7), N_PTS - 1);
  int o00, o01, o10, o11;
  float w00, w01, w10, w11, us;
  {
    float X = __ldg(G + n * 3 + 0);
    float Y = __ldg(G + n * 3 + 1);
    float Z = __ldg(G + n * 3 + 2);
    float px = T00 * X + T01 * Y + T02 * Z + T03;
    float py = T10 * X + T11 * Y + T12 * Z + T13;
    float pz = T20 * X + T21 * Y + T22 * Z + T23;
    float z  = fmaxf(pz, 1e-6f);
    float u  = fx * (px / z) + cx;
    float v  = fy * (py / z) + cy;
    float gx = 2.0f * u / Wm1 - 1.0f;
    float gy = 2.0f * v / Hm1 - 1.0f;
    float xs = fminf(fmaxf(((gx + 1.0f) * (float)W - 1.0f) * 0.5f, 0.0f), Wm1);
    float ys = fminf(fmaxf(((gy + 1.0f) * (float)H - 1.0f) * 0.5f, 0.0f), Hm1);
    float x0f = floorf(xs), y0f = floorf(ys);
    float x1f = fminf(x0f + 1.0f, Wm1), y1f = fminf(y0f + 1.0f, Hm1);
    float wx = xs - x0f, wy = ys - y0f;
    int x0 = (int)x0f, x1 = (int)x1f, y0 = (int)y0f, y1 = (int)y1f;
    w00 = (1.0f - wx) * (1.0f - wy); w01 = wx * (1.0f - wy);
    w10 = (1.0f - wx) * wy;          w11 = wx * wy;
    int r0 = y0 * W, r1 = y1 * W;
    us = w00 * __ldg(Ub + r0 + x0) + w01 * __ldg(Ub + r0 + x1)
       + w10 * __ldg(Ub + r1 + x0) + w11 * __ldg(Ub + r1 + x1);
    o00 = (r0 + x0) * 32; o01 = (r0 + x1) * 32;
    o10 = (r1 + x0) * 32; o11 = (r1 + x1) * 32;
  }

  float wacc = 0.0f;

  // typed load slots (use widest; narrower CPL uses .x / .x,.y only)
  if constexpr (CPL == 4) {
    const uint2* base = (const uint2*)Db;
    uint2 ca, cb, cc2, cd;
    float cw00, cw01, cw10, cw11, cus;
    {
      int a00 = __shfl_sync(0xffffffffu, o00, 0), a01 = __shfl_sync(0xffffffffu, o01, 0);
      int a10 = __shfl_sync(0xffffffffu, o10, 0), a11 = __shfl_sync(0xffffffffu, o11, 0);
      cw00 = __shfl_sync(0xffffffffu, w00, 0); cw01 = __shfl_sync(0xffffffffu, w01, 0);
      cw10 = __shfl_sync(0xffffffffu, w10, 0); cw11 = __shfl_sync(0xffffffffu, w11, 0);
      cus  = __shfl_sync(0xffffffffu, us,  0);
      ca = __ldg(base + a00 + lane); cb = __ldg(base + a01 + lane);
      cc2 = __ldg(base + a10 + lane); cd = __ldg(base + a11 + lane);
    }
    for (int p = 0; p < vc; p++) {
      uint2 na = {}, nb = {}, nc = {}, nd = {};
      float nw00 = 0, nw01 = 0, nw10 = 0, nw11 = 0, nus = 0;
      if (p + 1 < vc) {
        int a00 = __shfl_sync(0xffffffffu, o00, p + 1), a01 = __shfl_sync(0xffffffffu, o01, p + 1);
        int a10 = __shfl_sync(0xffffffffu, o10, p + 1), a11 = __shfl_sync(0xffffffffu, o11, p + 1);
        nw00 = __shfl_sync(0xffffffffu, w00, p + 1); nw01 = __shfl_sync(0xffffffffu, w01, p + 1);
        nw10 = __shfl_sync(0xffffffffu, w10, p + 1); nw11 = __shfl_sync(0xffffffffu, w11, p + 1);
        nus  = __shfl_sync(0xffffffffu, us,  p + 1);
        na = __ldg(base + a00 + lane); nb = __ldg(base + a01 + lane);
        nc = __ldg(base + a10 + lane); nd = __ldg(base + a11 + lane);
      }
      float2 a0 = __bfloat1622float2(*(__nv_bfloat162*)&ca.x);
      float2 a1 = __bfloat1622float2(*(__nv_bfloat162*)&ca.y);
      float2 b0 = __bfloat1622float2(*(__nv_bfloat162*)&cb.x);
      float2 b1 = __bfloat1622float2(*(__nv_bfloat162*)&cb.y);
      float2 c0v = __bfloat1622float2(*(__nv_bfloat162*)&cc2.x);
      float2 c1 = __bfloat1622float2(*(__nv_bfloat162*)&cc2.y);
      float2 d0v = __bfloat1622float2(*(__nv_bfloat162*)&cd.x);
      float2 d1 = __bfloat1622float2(*(__nv_bfloat162*)&cd.y);
      float e0 = cw00 * a0.x; e0 = fmaf(cw01, b0.x, e0); e0 = fmaf(cw10, c0v.x, e0); e0 = fmaf(cw11, d0v.x, e0);
      float e1 = cw00 * a0.y; e1 = fmaf(cw01, b0.y, e1); e1 = fmaf(cw10, c0v.y, e1); e1 = fmaf(cw11, d0v.y, e1);
      float e2 = cw00 * a1.x; e2 = fmaf(cw01, b1.x, e2); e2 = fmaf(cw10, c1.x, e2); e2 = fmaf(cw11, d1.x, e2);
      float e3 = cw00 * a1.y; e3 = fmaf(cw01, b1.y, e3); e3 = fmaf(cw10, c1.y, e3); e3 = fmaf(cw11, d1.y, e3);
      float spt = e0 * e0 + e1 * e1 + e2 * e2 + e3 * e3;
      wacc = fmaf(cus, spt, wacc);
      ca = na; cb = nb; cc2 = nc; cd = nd;
      cw00 = nw00; cw01 = nw01; cw10 = nw10; cw11 = nw11; cus = nus;
    }
  } else if constexpr (CPL == 2) {
    const unsigned* base = (const unsigned*)Db;
    unsigned ca, cb, cc2, cd;
    float cw00, cw01, cw10, cw11, cus;
    {
      int a00 = __shfl_sync(0xffffffffu, o00, 0), a01 = __shfl_sync(0xffffffffu, o01, 0);
      int a10 = __shfl_sync(0xffffffffu, o10, 0), a11 = __shfl_sync(0xffffffffu, o11, 0);
      cw00 = __shfl_sync(0xffffffffu, w00, 0); cw01 = __shfl_sync(0xffffffffu, w01, 0);
      cw10 = __shfl_sync(0xffffffffu, w10, 0); cw11 = __shfl_sync(0xffffffffu, w11, 0);
      cus  = __shfl_sync(0xffffffffu, us,  0);
      ca = __ldg(base + a00 + lane); cb = __ldg(base + a01 + lane);
      cc2 = __ldg(base + a10 + lane); cd = __ldg(base + a11 + lane);
    }
    for (int p = 0; p < vc; p++) {
      unsigned na = 0, nb = 0, nc = 0, nd = 0;
      float nw00 = 0, nw01 = 0, nw10 = 0, nw11 = 0, nus = 0;
      if (p + 1 < vc) {
        int a00 = __shfl_sync(0xffffffffu, o00, p + 1), a01 = __shfl_sync(0xffffffffu, o01, p + 1);
        int a10 = __shfl_sync(0xffffffffu, o10, p + 1), a11 = __shfl_sync(0xffffffffu, o11, p + 1);
        nw00 = __shfl_sync(0xffffffffu, w00, p + 1); nw01 = __shfl_sync(0xffffffffu, w01, p + 1);
        nw10 = __shfl_sync(0xffffffffu, w10, p + 1); nw11 = __shfl_sync(0xffffffffu, w11, p + 1);
        nus  = __shfl_sync(0xffffffffu, us,  p + 1);
        na = __ldg(base + a00 + lane); nb = __ldg(base + a01 + lane);
        nc = __ldg(base + a10 + lane); nd = __ldg(base + a11 + lane);
      }
      float2 a = __bfloat1622float2(*(__nv_bfloat162*)&ca);
      float2 bq = __bfloat1622float2(*(__nv_bfloat162*)&cb);
      float2 c = __bfloat1622float2(*(__nv_bfloat162*)&cc2);
      float2 d = __bfloat1622float2(*(__nv_bfloat162*)&cd);
      float e0 = cw00 * a.x; e0 = fmaf(cw01, bq.x, e0); e0 = fmaf(cw10, c.x, e0); e0 = fmaf(cw11, d.x, e0);
      float e1 = cw00 * a.y; e1 = fmaf(cw01, bq.y, e1); e1 = fmaf(cw10, c.y, e1); e1 = fmaf(cw11, d.y, e1);
      float spt = e0 * e0 + e1 * e1;
      wacc = fmaf(cus, spt, wacc);
      ca = na; cb = nb; cc2 = nc; cd = nd;
      cw00 = nw00; cw01 = nw01; cw10 = nw10; cw11 = nw11; cus = nus;
    }
  } else {
    __nv_bfloat16 ca, cb, cc2, cd;
    float cw00, cw01, cw10, cw11, cus;
    {
      int a00 = __shfl_sync(0xffffffffu, o00, 0), a01 = __shfl_sync(0xffffffffu, o01, 0);
      int a10 = __shfl_sync(0xffffffffu, o10, 0), a11 = __shfl_sync(0xffffffffu, o11, 0);
      cw00 = __shfl_sync(0xffffffffu, w00, 0); cw01 = __shfl_sync(0xffffffffu, w01, 0);
      cw10 = __shfl_sync(0xffffffffu, w10, 0); cw11 = __shfl_sync(0xffffffffu, w11, 0);
      cus  = __shfl_sync(0xffffffffu, us,  0);
      ca = __ldg(Db + a00 + lane); cb = __ldg(Db + a01 + lane);
      cc2 = __ldg(Db + a10 + lane); cd = __ldg(Db + a11 + lane);
    }
    for (int p = 0; p < vc; p++) {
      __nv_bfloat16 na = __float2bfloat16(0.f), nb = na, nc = na, nd = na;
      float nw00 = 0, nw01 = 0, nw10 = 0, nw11 = 0, nus = 0;
      if (p + 1 < vc) {
        int a00 = __shfl_sync(0xffffffffu, o00, p + 1), a01 = __shfl_sync(0xffffffffu, o01, p + 1);
        int a10 = __shfl_sync(0xffffffffu, o10, p + 1), a11 = __shfl_sync(0xffffffffu, o11, p + 1);
        nw00 = __shfl_sync(0xffffffffu, w00, p + 1); nw01 = __shfl_sync(0xffffffffu, w01, p + 1);
        nw10 = __shfl_sync(0xffffffffu, w10, p + 1); nw11 = __shfl_sync(0xffffffffu, w11, p + 1);
        nus  = __shfl_sync(0xffffffffu, us,  p + 1);
        na = __ldg(Db + a00 + lane); nb = __ldg(Db + a01 + lane);
        nc = __ldg(Db + a10 + lane); nd = __ldg(Db + a11 + lane);
      }
      float e0 = cw00 * __bfloat162float(ca);
      e0 = fmaf(cw01, __bfloat162float(cb), e0);
      e0 = fmaf(cw10, __bfloat162float(cc2), e0);
      e0 = fmaf(cw11, __bfloat162float(cd), e0);
      float spt = e0 * e0;
      wacc = fmaf(cus, spt, wacc);
      ca = na; cb = nb; cc2 = nc; cd = nd;
      cw00 = nw00; cw01 = nw01; cw10 = nw10; cw11 = nw11; cus = nus;
    }
  }

#pragma unroll
  for (int o = 16; o; o >>= 1) wacc += __shfl_xor_sync(0xffffffffu, wacc, o);
  __shared__ float wpar[8];
  if (lane == 0) wpar[w] = wacc;
  __syncthreads();
  if (threadIdx.x == 0) {
    float s = 0.0f;
#pragma unroll
    for (int ww = 0; ww < 8; ww++) s += wpar[ww];
    g_resacc[wpar_][slice][bm] = s;
  }
}

// ---------------------------------------------------------------------------
// final kernel: applies the 9th LM update, then geodesic + argmin + output.
// grid = B blocks x 144 threads. After iter 8: T_8 in g_Tbuf[0], res_8 in
// g_resacc[0].
// ---------------------------------------------------------------------------
__global__ void final_kernel(const float* __restrict__ Tpred, float* __restrict__ out,
                             float damping_last)
{
  int b = blockIdx.x;
  int m = threadIdx.x;
  __shared__ float tot[M_HYP];
  if (m < M_HYP) {
    float Tc[16];
    const float* Tsrc = g_Tbuf[0] + (size_t)(b * M_HYP + m) * 16;
#pragma unroll
    for (int i = 0; i < 16; i++) Tc[i] = Tsrc[i];
    float c = 0.0f;
    if (m < M16) {
      int bm = b * M16 + m;
      float rs = 0.0f;
#pragma unroll
      for (int p = 0; p < PS; p++) rs += g_resacc[0][p][bm];
      c = rs * (1.0f / N_PTS);
      apply_update(Tc, bm, 8, damping_last, c);
    }
    const float* P = Tpred + b * 16;
    float Ri[9] = { P[0], P[4], P[8],  P[1], P[5], P[9],  P[2], P[6], P[10] };
    float tix = -(Ri[0] * P[3] + Ri[1] * P[7] + Ri[2] * P[11]);
    float tiy = -(Ri[3] * P[3] + Ri[4] * P[7] + Ri[5] * P[11]);
    float tiz = -(Ri[6] * P[3] + Ri[7] * P[7] + Ri[8] * P[11]);
    float Ti[16] = { Ri[0], Ri[1], Ri[2], tix,
                     Ri[3], Ri[4], Ri[5], tiy,
                     Ri[6], Ri[7], Ri[8], tiz,
                     0.f, 0.f, 0.f, 1.f };
    float A[16];
#pragma unroll
    for (int i = 0; i < 4; i++)
#pragma unroll
      for (int j = 0; j < 4; j++)
        A[i * 4 + j] = Tc[i * 4 + 0] * Ti[0 * 4 + j] + Tc[i * 4 + 1] * Ti[1 * 4 + j]
                     + Tc[i * 4 + 2] * Ti[2 * 4 + j] + Tc[i * 4 + 3] * Ti[3 * 4 + j];
    float cos_a = (A[0] + A[5] + A[10] - 1.0f) * 0.5f;
    const float CL = (float)(1.0 - 1e-7);
    cos_a = fminf(fmaxf(cos_a, -CL), CL);
    float theta = acosf(cos_a);
    float th = fmaxf(theta, 1e-8f);
    float sn = fmaxf(sinf(th), 1e-8f);
    float wx = (A[9] - A[6]) / (2.0f * sn) * th;
    float wy = (A[2] - A[8]) / (2.0f * sn) * th;
    float wz = (A[4] - A[1]) / (2.0f * sn) * th;
    if (fabsf(theta) < 1e-6f) { wx = 0.f; wy = 0.f; wz = 0.f; }
    float tx = A[3], ty = A[7], tz = A[11];
    float geod = sqrtf(tx * tx + ty * ty + tz * tz + wx * wx + wy * wy + wz * wz);
    tot[m] = c + geod;
    out[128 + b * M_HYP + m] = c;
    float* Tdst = g_Tbuf[1] + (size_t)(b * M_HYP + m) * 16;
#pragma unroll
    for (int i = 0; i < 16; i++) Tdst[i] = Tc[i];
  }
  __syncthreads();
  if (m == 0) {
    int best = 0;
    float bv = tot[0];
    for (int i = 1; i < M_HYP; i++)
      if (tot[i] < bv) { bv = tot[i]; best = i; }
    const float* Tb = g_Tbuf[1] + (size_t)(b * M_HYP + best) * 16;
#pragma unroll
    for (int i = 0; i < 16; i++) out[b * 16 + i] = Tb[i];
  }
}

// ---------------------------------------------------------------------------
// Host launch
// ---------------------------------------------------------------------------
extern "C" void kernel_launch(void* const* d_in, const int* in_sizes, int n_in,
                              void* d_out, int out_size)
{
  const float* T_pred = (const float*)d_in[0];
  const float* geo    = (const float*)d_in[1];
  const float* Kin    = (const float*)d_in[2];
  const float* q0 = (const float*)d_in[3];
  const float* q1 = (const float*)d_in[4];
  const float* q2 = (const float*)d_in[5];
  const float* r0 = (const float*)d_in[6];
  const float* r1 = (const float*)d_in[7];
  const float* r2 = (const float*)d_in[8];
  const float* u0 = (const float*)d_in[9];
  const float* u1 = (const float*)d_in[10];
  const float* u2 = (const float*)d_in[11];
  float* out = (float*)d_out;

  __nv_bfloat16 *D0p, *D1p, *D2p;
  cudaGetSymbolAddress((void**)&D0p, g_D0);
  cudaGetSymbolAddress((void**)&D1p, g_D1);
  cudaGetSymbolAddress((void**)&D2p, g_D2);

  unsigned hk0, hk1;
  threefry2x32(0u, 42u, 0u, 0u, &hk0, &hk1);

  int prep_blocks = B_SZ + 1 + T0_TILES + T1_TILES + T2_TILES;
  prep_kernel<<<prep_blocks, 256>>>(q0, r0, q1, r1, q2, r2, D0p, D1p, D2p,
                                    T_pred, hk0, hk1);

  const int   lvl[N_ITER]  = {0, 0, 1, 1, 1, 2, 2, 2, 2};
  const float damp[3]      = {0.001f, 0.0005f, 0.00025f};
  const int   grid_res = B_SZ * M16 * PS;    // 1024 blocks
  for (int k = 0; k < N_ITER; k++) {
    int level = lvl[k];
    float scale = 1.0f / (4.0f / (float)(1 << level));
    float dprev = (k > 0) ? damp[lvl[k - 1]] : 0.0f;
    if (level == 0)
      residual_kernel<4><<<grid_res, 256>>>(D0p, u0, geo, Kin, C0, H0, W0, scale, k, dprev);
    else if (level == 1)
      residual_kernel<2><<<grid_res, 256>>>(D1p, u1, geo, Kin, C1, H1, W1, scale, k, dprev);
    else
      residual_kernel<1><<<grid_res, 256>>>(D2p, u2, geo, Kin, C2, H2, W2, scale, k, dprev);
  }

  final_kernel<<<B_SZ, M_HYP>>>(T_pred, out, damp[2]);
  (void)in_sizes; (void)n_in; (void)out_size;
}